// round 9
// baseline (speedup 1.0000x reference)
#include <cuda_runtime.h>
#include <cuda_bf16.h>
#include <math.h>
#include <stdint.h>

constexpr int SEQ  = 1576;   // T*N tokens
constexpr int DIM  = 768;
constexpr int NHEAD = 12;
constexpr int HD   = 64;
constexpr int TFR  = 8;      // frames
constexpr int NTOK = 197;    // tokens per frame
constexpr int NPAT = 196;
constexpr int MLPD = 3072;
constexpr int QKVD = 2304;
constexpr float ASCALE = 0.125f;
#define QB 8

// ---------------- scratch (no allocation allowed) ----------------
__device__ float g_emb[1568 * 768];
__device__ float g_h[SEQ * DIM];
__device__ float g_qkv[SEQ * QKVD];
__device__ float g_vmean[NHEAD * TFR * HD];
__device__ unsigned short g_p_hi[1568 * 768],  g_p_lo[1568 * 768];
__device__ unsigned short g_a_hi[SEQ * DIM],   g_a_lo[SEQ * DIM];
__device__ unsigned short g_o_hi[SEQ * DIM],   g_o_lo[SEQ * DIM];
__device__ unsigned short g_m_hi[SEQ * MLPD],  g_m_lo[SEQ * MLPD];
__device__ unsigned short g_wp_hi[DIM * DIM],        g_wp_lo[DIM * DIM];
__device__ unsigned short g_qkvT_hi[12 * QKVD * DIM], g_qkvT_lo[12 * QKVD * DIM];
__device__ unsigned short g_projT_hi[12 * DIM * DIM], g_projT_lo[12 * DIM * DIM];
__device__ unsigned short g_fc1T_hi[12 * MLPD * DIM], g_fc1T_lo[12 * MLPD * DIM];
__device__ unsigned short g_fc2T_hi[12 * DIM * MLPD], g_fc2T_lo[12 * DIM * MLPD];

// ================= helpers =================
__device__ __forceinline__ uint32_t smem_u32(const void* p) {
    uint32_t a;
    asm("{ .reg .u64 t; cvta.to.shared.u64 t, %1; cvt.u32.u64 %0, t; }" : "=r"(a) : "l"(p));
    return a;
}
__device__ __forceinline__ void split1(float v, unsigned short& hi, unsigned short& lo) {
    __nv_bfloat16 h = __float2bfloat16(v);
    __nv_bfloat16 l = __float2bfloat16(v - __bfloat162float(h));
    hi = __bfloat16_as_ushort(h);
    lo = __bfloat16_as_ushort(l);
}

#define LDM4(r, addr) \
    asm volatile("ldmatrix.sync.aligned.m8n8.x4.shared.b16 {%0,%1,%2,%3}, [%4];" \
        : "=r"((r)[0]), "=r"((r)[1]), "=r"((r)[2]), "=r"((r)[3]) : "r"(addr))

#define MMA_BF16(c, a, b0, b1) \
    asm volatile("mma.sync.aligned.m16n8k16.row.col.f32.bf16.bf16.f32 " \
        "{%0,%1,%2,%3}, {%4,%5,%6,%7}, {%8,%9}, {%0,%1,%2,%3};" \
        : "+f"((c)[0]), "+f"((c)[1]), "+f"((c)[2]), "+f"((c)[3]) \
        : "r"((a)[0]), "r"((a)[1]), "r"((a)[2]), "r"((a)[3]), "r"(b0), "r"(b1))

#define CPA16(dst, src, sz) \
    asm volatile("cp.async.cg.shared.global [%0], [%1], 16, %2;" \
        :: "r"(dst), "l"(src), "r"(sz))
#define CPA_COMMIT() asm volatile("cp.async.commit_group;")
#define CPA_WAIT1()  asm volatile("cp.async.wait_group 1;")

// ---------------- transpose + split: fp32 [K,N] -> bf16 hi/lo [N,K] ----------------
__global__ void transpose_split_kernel(const float* __restrict__ in,
        unsigned short* __restrict__ ohi, unsigned short* __restrict__ olo, int K, int N) {
    __shared__ float t[32][33];
    size_t base = (size_t)blockIdx.z * K * N;
    int n0 = blockIdx.x * 32, k0 = blockIdx.y * 32;
    int tx = threadIdx.x, ty = threadIdx.y;
    #pragma unroll
    for (int j = 0; j < 32; j += 8)
        t[ty + j][tx] = in[base + (size_t)(k0 + ty + j) * N + n0 + tx];
    __syncthreads();
    #pragma unroll
    for (int j = 0; j < 32; j += 8) {
        unsigned short hi, lo;
        split1(t[tx][ty + j], hi, lo);
        size_t o = base + (size_t)(n0 + ty + j) * K + k0 + tx;
        ohi[o] = hi; olo[o] = lo;
    }
}

// ---------------- elementwise split ----------------
__global__ void split_kernel(const float* __restrict__ in,
        unsigned short* __restrict__ hi, unsigned short* __restrict__ lo, int n) {
    int i = blockIdx.x * blockDim.x + threadIdx.x;
    if (i >= n) return;
    split1(in[i], hi[i], lo[i]);
}

// ===================================================================================
// bf16x3 MMA GEMM, M-tile 64 (for qkv/fc1): 64x128, 256 thr, 2 CTA/SM
// ===================================================================================
constexpr int RS = 80;
constexpr int NSTG = 3;
constexpr int AL_OFF = 64 * RS;
constexpr int BH_OFF = 2 * 64 * RS;
constexpr int BL_OFF = BH_OFF + 128 * RS;
constexpr int STG    = BH_OFF + 2 * 128 * RS;   // 30720

__device__ __forceinline__ void load_stage(uint32_t sb,
        const unsigned short* __restrict__ Ahi, const unsigned short* __restrict__ Alo,
        const unsigned short* __restrict__ Bhi, const unsigned short* __restrict__ Blo,
        int row0, int col0, int K, int k0, int M, int tid) {
    int r = tid >> 2, ch = tid & 3;
    uint32_t doff = (uint32_t)(r * RS + ch * 16);
    size_t asrc = (size_t)(row0 + r) * K + k0 + ch * 8;
    int av = (row0 + r < M) ? 16 : 0;
    CPA16(sb + doff, Ahi + asrc, av);
    CPA16(sb + AL_OFF + doff, Alo + asrc, av);
    size_t b0 = (size_t)(col0 + r) * K + k0 + ch * 8;
    size_t b1 = (size_t)(col0 + 64 + r) * K + k0 + ch * 8;
    CPA16(sb + BH_OFF + doff, Bhi + b0, 16);
    CPA16(sb + BH_OFF + doff + 64 * RS, Bhi + b1, 16);
    CPA16(sb + BL_OFF + doff, Blo + b0, 16);
    CPA16(sb + BL_OFF + doff + 64 * RS, Blo + b1, 16);
    CPA_COMMIT();
}

__device__ __forceinline__ void epi_store(float v0, float v1, const float* bias,
        const float* res, float* C, unsigned short* Chi, unsigned short* Clo,
        int gm, int col, int N, int act) {
    if (bias) { float2 bb = *(const float2*)(bias + col); v0 += bb.x; v1 += bb.y; }
    if (act) {
        v0 = 0.5f * v0 * (1.f + erff(v0 * 0.70710678118f));
        v1 = 0.5f * v1 * (1.f + erff(v1 * 0.70710678118f));
    }
    size_t o = (size_t)gm * N + col;
    if (res) {
        float2 rv = *(const float2*)(res + o);
        v0 += rv.x; v1 += rv.y;
    }
    if (Chi) {
        unsigned short h0, l0, h1, l1;
        split1(v0, h0, l0);
        split1(v1, h1, l1);
        *(uint32_t*)(Chi + o) = (uint32_t)h0 | ((uint32_t)h1 << 16);
        *(uint32_t*)(Clo + o) = (uint32_t)l0 | ((uint32_t)l1 << 16);
    } else {
        *(float2*)(C + o) = make_float2(v0, v1);
    }
}

__global__ void __launch_bounds__(256, 2) mma_gemm(
        const unsigned short* __restrict__ Ahi, const unsigned short* __restrict__ Alo,
        const unsigned short* __restrict__ Bhi, const unsigned short* __restrict__ Blo,
        const float* __restrict__ bias, const float* __restrict__ res,
        float* __restrict__ C, unsigned short* __restrict__ Chi,
        unsigned short* __restrict__ Clo,
        int M, int N, int K, int act) {
    extern __shared__ __align__(128) char sm[];
    const int tid = threadIdx.x;
    const int lane = tid & 31, wid = tid >> 5;
    const int wm = wid & 1, wn = wid >> 1;
    const int row0 = blockIdx.y * 64, col0 = blockIdx.x * 128;
    const uint32_t smb = smem_u32(sm);

    const int a_row = ((lane >> 3) & 1) * 8 + (lane & 7);
    const int a_kb  = (lane >> 4) * 16;
    const int b_row = (lane >> 4) * 8 + (lane & 7);
    const int b_kb  = ((lane >> 3) & 1) * 16;

    float c[2][4][4];
    #pragma unroll
    for (int i = 0; i < 2; i++)
        #pragma unroll
        for (int j = 0; j < 4; j++)
            #pragma unroll
            for (int k = 0; k < 4; k++) c[i][j][k] = 0.f;

    const int nk = K >> 5;
    load_stage(smb, Ahi, Alo, Bhi, Blo, row0, col0, K, 0, M, tid);
    load_stage(smb + STG, Ahi, Alo, Bhi, Blo, row0, col0, K, 32, M, tid);

    int buf = 0;
    for (int it = 0; it < nk; it++) {
        CPA_WAIT1();
        __syncthreads();
        if (it + 2 < nk) {
            int nb = buf + 2; if (nb >= NSTG) nb -= NSTG;
            load_stage(smb + (uint32_t)nb * STG, Ahi, Alo, Bhi, Blo,
                       row0, col0, K, (it + 2) << 5, M, tid);
        }
        uint32_t sb = smb + (uint32_t)buf * STG;
        #pragma unroll
        for (int kk = 0; kk < 2; kk++) {
            uint32_t bh[8], bl[8];
            #pragma unroll
            for (int nip = 0; nip < 2; nip++) {
                uint32_t baddr = sb + BH_OFF + (wn * 32 + nip * 16 + b_row) * RS + b_kb + kk * 32;
                LDM4(&bh[nip * 4], baddr);
                LDM4(&bl[nip * 4], baddr + (BL_OFF - BH_OFF));
            }
            #pragma unroll
            for (int mi = 0; mi < 2; mi++) {
                uint32_t ah[4], al[4];
                uint32_t aaddr = sb + (wm * 32 + mi * 16 + a_row) * RS + a_kb + kk * 32;
                LDM4(ah, aaddr);
                LDM4(al, aaddr + AL_OFF);
                #pragma unroll
                for (int ni = 0; ni < 4; ni++) {
                    uint32_t b0h = bh[(ni >> 1) * 4 + (ni & 1) * 2];
                    uint32_t b1h = bh[(ni >> 1) * 4 + (ni & 1) * 2 + 1];
                    uint32_t b0l = bl[(ni >> 1) * 4 + (ni & 1) * 2];
                    uint32_t b1l = bl[(ni >> 1) * 4 + (ni & 1) * 2 + 1];
                    MMA_BF16(c[mi][ni], ah, b0h, b1h);
                    MMA_BF16(c[mi][ni], ah, b0l, b1l);
                    MMA_BF16(c[mi][ni], al, b0h, b1h);
                }
            }
        }
        buf++; if (buf >= NSTG) buf = 0;
    }

    const int g = lane >> 2, t = lane & 3;
    #pragma unroll
    for (int mi = 0; mi < 2; mi++) {
        #pragma unroll
        for (int ni = 0; ni < 4; ni++) {
            int col = col0 + wn * 32 + ni * 8 + t * 2;
            #pragma unroll
            for (int half = 0; half < 2; half++) {
                int gm = row0 + wm * 32 + mi * 16 + g + half * 8;
                if (gm >= M) continue;
                epi_store(c[mi][ni][half * 2], c[mi][ni][half * 2 + 1],
                          bias, res, C, Chi, Clo, gm, col, N, act);
            }
        }
    }
}

// ===================================================================================
// bf16x3 MMA GEMM, M-tile 32 (for patch/proj/fc2 where grid would be ~150):
// 32x128 tile, 256 thr, 8 warps 1x8 (warp tile 32x16), 2 CTA/SM via 25.6KB stages.
// ===================================================================================
constexpr int AL32 = 32 * RS;          // 2560
constexpr int BH32 = 2 * 32 * RS;      // 5120
constexpr int BL32 = BH32 + 128 * RS;  // 15360
constexpr int STG32 = BH32 + 2 * 128 * RS;  // 25600

__device__ __forceinline__ void load_stage32(uint32_t sb,
        const unsigned short* __restrict__ Ahi, const unsigned short* __restrict__ Alo,
        const unsigned short* __restrict__ Bhi, const unsigned short* __restrict__ Blo,
        int row0, int col0, int K, int k0, int M, int tid) {
    #pragma unroll
    for (int c = tid; c < 160 * 4; c += 256) {
        int r = c >> 2, ch = c & 3;
        if (r < 32) {
            uint32_t doff = (uint32_t)(r * RS + ch * 16);
            size_t asrc = (size_t)(row0 + r) * K + k0 + ch * 8;
            int av = (row0 + r < M) ? 16 : 0;
            CPA16(sb + doff, Ahi + asrc, av);
            CPA16(sb + AL32 + doff, Alo + asrc, av);
        } else {
            int rr = r - 32;
            uint32_t boff = (uint32_t)(rr * RS + ch * 16);
            size_t bsrc = (size_t)(col0 + rr) * K + k0 + ch * 8;
            CPA16(sb + BH32 + boff, Bhi + bsrc, 16);
            CPA16(sb + BL32 + boff, Blo + bsrc, 16);
        }
    }
    CPA_COMMIT();
}

__global__ void __launch_bounds__(256, 2) mma_gemm32(
        const unsigned short* __restrict__ Ahi, const unsigned short* __restrict__ Alo,
        const unsigned short* __restrict__ Bhi, const unsigned short* __restrict__ Blo,
        const float* __restrict__ bias, const float* __restrict__ res,
        float* __restrict__ C, unsigned short* __restrict__ Chi,
        unsigned short* __restrict__ Clo,
        int M, int N, int K, int act) {
    extern __shared__ __align__(128) char sm[];
    const int tid = threadIdx.x;
    const int lane = tid & 31, wid = tid >> 5;   // wn = wid, 16 cols each
    const int row0 = blockIdx.y * 32, col0 = blockIdx.x * 128;
    const uint32_t smb = smem_u32(sm);

    const int a_row = ((lane >> 3) & 1) * 8 + (lane & 7);
    const int a_kb  = (lane >> 4) * 16;
    const int b_row = (lane >> 4) * 8 + (lane & 7);
    const int b_kb  = ((lane >> 3) & 1) * 16;

    float c[2][2][4];
    #pragma unroll
    for (int i = 0; i < 2; i++)
        #pragma unroll
        for (int j = 0; j < 2; j++)
            #pragma unroll
            for (int k = 0; k < 4; k++) c[i][j][k] = 0.f;

    const int nk = K >> 5;
    load_stage32(smb, Ahi, Alo, Bhi, Blo, row0, col0, K, 0, M, tid);
    load_stage32(smb + STG32, Ahi, Alo, Bhi, Blo, row0, col0, K, 32, M, tid);

    int buf = 0;
    for (int it = 0; it < nk; it++) {
        CPA_WAIT1();
        __syncthreads();
        if (it + 2 < nk) {
            int nb = buf + 2; if (nb >= NSTG) nb -= NSTG;
            load_stage32(smb + (uint32_t)nb * STG32, Ahi, Alo, Bhi, Blo,
                         row0, col0, K, (it + 2) << 5, M, tid);
        }
        uint32_t sb = smb + (uint32_t)buf * STG32;
        #pragma unroll
        for (int kk = 0; kk < 2; kk++) {
            uint32_t bh[4], bl[4];
            uint32_t baddr = sb + BH32 + (wid * 16 + b_row) * RS + b_kb + kk * 32;
            LDM4(bh, baddr);
            LDM4(bl, baddr + (BL32 - BH32));
            #pragma unroll
            for (int mi = 0; mi < 2; mi++) {
                uint32_t ah[4], al[4];
                uint32_t aaddr = sb + (mi * 16 + a_row) * RS + a_kb + kk * 32;
                LDM4(ah, aaddr);
                LDM4(al, aaddr + AL32);
                #pragma unroll
                for (int ni = 0; ni < 2; ni++) {
                    uint32_t b0h = bh[ni * 2], b1h = bh[ni * 2 + 1];
                    uint32_t b0l = bl[ni * 2], b1l = bl[ni * 2 + 1];
                    MMA_BF16(c[mi][ni], ah, b0h, b1h);
                    MMA_BF16(c[mi][ni], ah, b0l, b1l);
                    MMA_BF16(c[mi][ni], al, b0h, b1h);
                }
            }
        }
        buf++; if (buf >= NSTG) buf = 0;
    }

    const int g = lane >> 2, t = lane & 3;
    #pragma unroll
    for (int mi = 0; mi < 2; mi++) {
        #pragma unroll
        for (int ni = 0; ni < 2; ni++) {
            int col = col0 + wid * 16 + ni * 8 + t * 2;
            #pragma unroll
            for (int half = 0; half < 2; half++) {
                int gm = row0 + mi * 16 + g + half * 8;
                if (gm >= M) continue;
                epi_store(c[mi][ni][half * 2], c[mi][ni][half * 2 + 1],
                          bias, res, C, Chi, Clo, gm, col, N, act);
            }
        }
    }
}

// ---------------- patch extraction -> bf16 hi/lo ----------------
__global__ void patch_kernel(const float* __restrict__ x,
        unsigned short* __restrict__ Phi, unsigned short* __restrict__ Plo) {
    int idx = blockIdx.x * blockDim.x + threadIdx.x;
    if (idx >= 1568 * 768) return;
    int m = idx / 768, kcol = idx % 768;
    int t = m / 196, n = m % 196;
    int hp = n / 14, wp = n % 14;
    int c = kcol / 256, rem = kcol % 256;
    int ii = rem / 16, jj = rem % 16;
    float v = x[((t * 3 + c) * 224 + hp * 16 + ii) * 224 + wp * 16 + jj];
    split1(v, Phi[idx], Plo[idx]);
}

// ---------------- assemble h ----------------
__global__ void assemble_kernel(const float* __restrict__ emb, const float* __restrict__ cls,
                                const float* __restrict__ pos, float* __restrict__ h) {
    int idx = blockIdx.x * blockDim.x + threadIdx.x;
    if (idx >= SEQ * DIM) return;
    int m = idx / DIM, dd = idx % DIM;
    int t = m / NTOK, r = m % NTOK;
    float v;
    if (r == 0) {
        v = cls[dd] + pos[dd];
    } else {
        int pp = r - 1;
        int f = pp * DIM + dd;
        int n = f % NPAT, dc = f / NPAT;
        v = emb[(t * NPAT + n) * DIM + dc] + pos[(1 + pp) * DIM + dd];
    }
    h[idx] = v;
}

// ---------------- block reduction ----------------
__device__ __forceinline__ float block_sum256(float v, float* sh) {
    #pragma unroll
    for (int o = 16; o; o >>= 1) v += __shfl_xor_sync(0xffffffffu, v, o);
    if ((threadIdx.x & 31) == 0) sh[threadIdx.x >> 5] = v;
    __syncthreads();
    float t = 0.f;
    #pragma unroll
    for (int i = 0; i < 8; i++) t += sh[i];
    __syncthreads();
    return t;
}

// ---------------- LayerNorm -> bf16 hi/lo ----------------
__global__ void ln_split_kernel(const float* __restrict__ x, const float* __restrict__ g,
        const float* __restrict__ b, unsigned short* __restrict__ yhi,
        unsigned short* __restrict__ ylo) {
    __shared__ float sh[8];
    int row = blockIdx.x, tid = threadIdx.x;
    const float* xr = x + (size_t)row * DIM;
    float v0 = xr[tid], v1 = xr[tid + 256], v2 = xr[tid + 512];
    float mean = block_sum256(v0 + v1 + v2, sh) * (1.f / DIM);
    float d0 = v0 - mean, d1 = v1 - mean, d2 = v2 - mean;
    float var = block_sum256(d0 * d0 + d1 * d1 + d2 * d2, sh) * (1.f / DIM);
    float inv = rsqrtf(var + 1e-5f);
    size_t o = (size_t)row * DIM + tid;
    float y0 = d0 * inv * g[tid]       + b[tid];
    float y1 = d1 * inv * g[tid + 256] + b[tid + 256];
    float y2 = d2 * inv * g[tid + 512] + b[tid + 512];
    split1(y0, yhi[o],       ylo[o]);
    split1(y1, yhi[o + 256], ylo[o + 256]);
    split1(y2, yhi[o + 512], ylo[o + 512]);
}

// ---------------- final LayerNorm (fp32 out) ----------------
__global__ void ln_kernel(const float* __restrict__ x, const float* __restrict__ g,
                          const float* __restrict__ b, float* __restrict__ y) {
    __shared__ float sh[8];
    int row = blockIdx.x, tid = threadIdx.x;
    const float* xr = x + (size_t)row * DIM;
    float v0 = xr[tid], v1 = xr[tid + 256], v2 = xr[tid + 512];
    float mean = block_sum256(v0 + v1 + v2, sh) * (1.f / DIM);
    float d0 = v0 - mean, d1 = v1 - mean, d2 = v2 - mean;
    float var = block_sum256(d0 * d0 + d1 * d1 + d2 * d2, sh) * (1.f / DIM);
    float inv = rsqrtf(var + 1e-5f);
    float* yr = y + (size_t)row * DIM;
    yr[tid]       = d0 * inv * g[tid]       + b[tid];
    yr[tid + 256] = d1 * inv * g[tid + 256] + b[tid + 256];
    yr[tid + 512] = d2 * inv * g[tid + 512] + b[tid + 512];
}

// ---------------- temporal v-mean ----------------
__global__ void vmean_kernel(const float* __restrict__ qkv, float* __restrict__ vmean) {
    int ht = blockIdx.x;
    int t = ht % TFR, h = ht / TFR;
    int d = threadIdx.x;
    float s = 0.f;
    for (int n = 0; n < NTOK; n++)
        s += qkv[(size_t)(t * NTOK + n) * QKVD + 2 * DIM + h * HD + d];
    vmean[ht * HD + d] = s * (1.f / NTOK);
}

// ---------------- attention (QB=8, 4-key register-blocked scores) ----------------
__global__ void attn_kernel(const float* __restrict__ qkv, const float* __restrict__ vmean,
        unsigned short* __restrict__ ohi, unsigned short* __restrict__ olo,
        int keyLen, int keyLenP, int numSeg) {
    extern __shared__ float smf[];
    float* qs  = smf;                       // QB*HD
    float* sc  = smf + QB * HD;             // QB*keyLenP
    float* red = sc + QB * keyLenP;         // 4*QB*HD
    __shared__ float wsum[QB];
    int tid = threadIdx.x;
    int hseg = blockIdx.y;
    int h = hseg / numSeg, seg = hseg % numSeg;
    int base = seg * keyLen;
    int q0 = blockIdx.x * QB;
    int nq = min(QB, keyLen - q0);

    for (int i = tid; i < QB * HD; i += 256) {
        int qi = i / HD, d = i % HD;
        qs[i] = (qi < nq) ? qkv[(size_t)(base + q0 + qi) * QKVD + h * HD + d] : 0.f;
    }
    __syncthreads();

    const int nkb = (keyLen + 3) >> 2;
    for (int kb = tid; kb < nkb; kb += 256) {
        int kk = kb << 2;
        float acc[QB][4];
        #pragma unroll
        for (int qi = 0; qi < QB; qi++)
            #pragma unroll
            for (int c = 0; c < 4; c++) acc[qi][c] = 0.f;
        const float* kbase0 = qkv + (size_t)(base + kk) * QKVD + DIM + h * HD;
        int v1 = (kk + 1 < keyLen) ? 1 : 0;
        int v2 = (kk + 2 < keyLen) ? 2 : 0;
        int v3 = (kk + 3 < keyLen) ? 3 : 0;
        #pragma unroll 4
        for (int j = 0; j < 16; j++) {
            float4 k0 = *(const float4*)(kbase0 + (size_t)0  * QKVD + j * 4);
            float4 k1 = *(const float4*)(kbase0 + (size_t)v1 * QKVD + j * 4);
            float4 k2 = *(const float4*)(kbase0 + (size_t)v2 * QKVD + j * 4);
            float4 k3 = *(const float4*)(kbase0 + (size_t)v3 * QKVD + j * 4);
            #pragma unroll
            for (int qi = 0; qi < QB; qi++) {
                float4 q = *(const float4*)(qs + qi * HD + j * 4);
                acc[qi][0] += q.x * k0.x + q.y * k0.y + q.z * k0.z + q.w * k0.w;
                acc[qi][1] += q.x * k1.x + q.y * k1.y + q.z * k1.z + q.w * k1.w;
                acc[qi][2] += q.x * k2.x + q.y * k2.y + q.z * k2.z + q.w * k2.w;
                acc[qi][3] += q.x * k3.x + q.y * k3.y + q.z * k3.z + q.w * k3.w;
            }
        }
        #pragma unroll
        for (int qi = 0; qi < QB; qi++) {
            float* dst = sc + qi * keyLenP + kk;
            if (kk + 3 < keyLen) {
                *(float4*)dst = make_float4(acc[qi][0] * ASCALE, acc[qi][1] * ASCALE,
                                            acc[qi][2] * ASCALE, acc[qi][3] * ASCALE);
            } else {
                for (int c = 0; c < 4; c++)
                    if (kk + c < keyLen) dst[c] = acc[qi][c] * ASCALE;
            }
        }
    }
    __syncthreads();

    int w = tid >> 5, lane = tid & 31;
    if (w < nq) {
        float mx = -1e30f;
        for (int kk = lane; kk < keyLen; kk += 32) mx = fmaxf(mx, sc[w * keyLenP + kk]);
        #pragma unroll
        for (int off = 16; off; off >>= 1) mx = fmaxf(mx, __shfl_xor_sync(0xffffffffu, mx, off));
        float sum = 0.f;
        for (int kk = lane; kk < keyLen; kk += 32) {
            float e = __expf(sc[w * keyLenP + kk] - mx);
            sc[w * keyLenP + kk] = e;
            sum += e;
        }
        #pragma unroll
        for (int off = 16; off; off >>= 1) sum += __shfl_xor_sync(0xffffffffu, sum, off);
        if (lane == 0) wsum[w] = sum;
    }
    __syncthreads();

    int d = tid & 63, part = tid >> 6;
    float acc[QB];
    #pragma unroll
    for (int qi = 0; qi < QB; qi++) acc[qi] = 0.f;
    for (int kk = part; kk < keyLen; kk += 4) {
        float v = qkv[(size_t)(base + kk) * QKVD + 2 * DIM + h * HD + d];
        #pragma unroll
        for (int qi = 0; qi < QB; qi++)
            if (qi < nq) acc[qi] += sc[qi * keyLenP + kk] * v;
    }
    #pragma unroll
    for (int qi = 0; qi < QB; qi++)
        red[(part * QB + qi) * HD + d] = acc[qi];
    __syncthreads();
    if (part == 0) {
        for (int qi = 0; qi < nq; qi++) {
            float s = red[qi * HD + d] + red[(QB + qi) * HD + d]
                    + red[(2 * QB + qi) * HD + d] + red[(3 * QB + qi) * HD + d];
            s /= wsum[qi];
            if (vmean) s += vmean[hseg * HD + d];
            size_t o = (size_t)(base + q0 + qi) * DIM + h * HD + d;
            split1(s, ohi[o], olo[o]);
        }
    }
}

// ---------------- host ----------------
static void run_mma(const unsigned short* Ahi, const unsigned short* Alo,
                    const unsigned short* Bhi, const unsigned short* Blo,
                    const float* bias, const float* res, float* C,
                    unsigned short* Chi, unsigned short* Clo,
                    int M, int N, int K, int act) {
    dim3 grid(N / 128, (M + 63) / 64);
    mma_gemm<<<grid, 256, NSTG * STG>>>(Ahi, Alo, Bhi, Blo, bias, res, C, Chi, Clo, M, N, K, act);
}
static void run_mma32(const unsigned short* Ahi, const unsigned short* Alo,
                      const unsigned short* Bhi, const unsigned short* Blo,
                      const float* bias, const float* res, float* C,
                      unsigned short* Chi, unsigned short* Clo,
                      int M, int N, int K, int act) {
    dim3 grid(N / 128, (M + 31) / 32);
    mma_gemm32<<<grid, 256, NSTG * STG32>>>(Ahi, Alo, Bhi, Blo, bias, res, C, Chi, Clo, M, N, K, act);
}

extern "C" void kernel_launch(void* const* d_in, const int* in_sizes, int n_in,
                              void* d_out, int out_size) {
    const float* x       = (const float*)d_in[0];
    const float* W_patch = (const float*)d_in[1];
    const float* b_patch = (const float*)d_in[2];
    const float* cls     = (const float*)d_in[3];
    const float* pos     = (const float*)d_in[4];
    const float* ln1_g   = (const float*)d_in[5];
    const float* ln1_b   = (const float*)d_in[6];
    const float* qkv_w   = (const float*)d_in[7];
    const float* qkv_b   = (const float*)d_in[8];
    const float* proj_w  = (const float*)d_in[9];
    const float* proj_b  = (const float*)d_in[10];
    const float* ln2_g   = (const float*)d_in[11];
    const float* ln2_b   = (const float*)d_in[12];
    const float* fc1_w   = (const float*)d_in[13];
    const float* fc1_b   = (const float*)d_in[14];
    const float* fc2_w   = (const float*)d_in[15];
    const float* fc2_b   = (const float*)d_in[16];
    const float* lnf_g   = (const float*)d_in[17];
    const float* lnf_b   = (const float*)d_in[18];

    float *emb_, *h_, *qkv_, *vm_;
    unsigned short *pH, *pL, *aH, *aL, *oH, *oL, *mH, *mL;
    unsigned short *wpH, *wpL, *qkH, *qkL, *prH, *prL, *f1H, *f1L, *f2H, *f2L;
    cudaGetSymbolAddress((void**)&emb_, g_emb);
    cudaGetSymbolAddress((void**)&h_,   g_h);
    cudaGetSymbolAddress((void**)&qkv_, g_qkv);
    cudaGetSymbolAddress((void**)&vm_,  g_vmean);
    cudaGetSymbolAddress((void**)&pH, g_p_hi);   cudaGetSymbolAddress((void**)&pL, g_p_lo);
    cudaGetSymbolAddress((void**)&aH, g_a_hi);   cudaGetSymbolAddress((void**)&aL, g_a_lo);
    cudaGetSymbolAddress((void**)&oH, g_o_hi);   cudaGetSymbolAddress((void**)&oL, g_o_lo);
    cudaGetSymbolAddress((void**)&mH, g_m_hi);   cudaGetSymbolAddress((void**)&mL, g_m_lo);
    cudaGetSymbolAddress((void**)&wpH, g_wp_hi); cudaGetSymbolAddress((void**)&wpL, g_wp_lo);
    cudaGetSymbolAddress((void**)&qkH, g_qkvT_hi); cudaGetSymbolAddress((void**)&qkL, g_qkvT_lo);
    cudaGetSymbolAddress((void**)&prH, g_projT_hi); cudaGetSymbolAddress((void**)&prL, g_projT_lo);
    cudaGetSymbolAddress((void**)&f1H, g_fc1T_hi); cudaGetSymbolAddress((void**)&f1L, g_fc1T_lo);
    cudaGetSymbolAddress((void**)&f2H, g_fc2T_hi); cudaGetSymbolAddress((void**)&f2L, g_fc2T_lo);

    cudaFuncSetAttribute(mma_gemm,   cudaFuncAttributeMaxDynamicSharedMemorySize, NSTG * STG);
    cudaFuncSetAttribute(mma_gemm32, cudaFuncAttributeMaxDynamicSharedMemorySize, NSTG * STG32);

    size_t smem_joint = (size_t)(QB * HD + QB * SEQ  + 4 * QB * HD) * sizeof(float);
    size_t smem_sp    = (size_t)(QB * HD + QB * 200  + 4 * QB * HD) * sizeof(float);
    cudaFuncSetAttribute(attn_kernel, cudaFuncAttributeMaxDynamicSharedMemorySize, (int)smem_joint);

    patch_kernel<<<(1568 * 768 + 255) / 256, 256>>>(x, pH, pL);                       // 0
    split_kernel<<<(DIM * DIM + 255) / 256, 256>>>(W_patch, wpH, wpL, DIM * DIM);     // 1
    dim3 tb(32, 8);
    transpose_split_kernel<<<dim3(QKVD / 32, DIM / 32, 12), tb>>>(qkv_w, qkH, qkL, DIM, QKVD); // 2
    run_mma32(pH, pL, wpH, wpL, b_patch, nullptr, emb_, nullptr, nullptr, 1568, 768, 768, 0);  // 3 <- profiled
    transpose_split_kernel<<<dim3(DIM / 32,  DIM / 32, 12), tb>>>(proj_w, prH, prL, DIM, DIM);
    transpose_split_kernel<<<dim3(MLPD / 32, DIM / 32, 12), tb>>>(fc1_w,  f1H, f1L, DIM, MLPD);
    transpose_split_kernel<<<dim3(DIM / 32, MLPD / 32, 12), tb>>>(fc2_w,  f2H, f2L, MLPD, DIM);
    assemble_kernel<<<(SEQ * DIM + 255) / 256, 256>>>(emb_, cls, pos, h_);

    for (int i = 0; i < 12; i++) {
        ln_split_kernel<<<SEQ, 256>>>(h_, ln1_g + i * DIM, ln1_b + i * DIM, aH, aL);
        run_mma(aH, aL, qkH + (size_t)i * QKVD * DIM, qkL + (size_t)i * QKVD * DIM,
                qkv_b + i * QKVD, nullptr, qkv_, nullptr, nullptr, SEQ, QKVD, DIM, 0);
        if ((i & 1) == 0) {
            vmean_kernel<<<NHEAD * TFR, HD>>>(qkv_, vm_);
            dim3 g((NTOK + QB - 1) / QB, NHEAD * TFR);
            attn_kernel<<<g, 256, smem_sp>>>(qkv_, vm_, oH, oL, NTOK, 200, TFR);
        } else {
            dim3 g((SEQ + QB - 1) / QB, NHEAD);
            attn_kernel<<<g, 256, smem_joint>>>(qkv_, nullptr, oH, oL, SEQ, SEQ, 1);
        }
        run_mma32(oH, oL, prH + (size_t)i * DIM * DIM, prL + (size_t)i * DIM * DIM,
                  proj_b + i * DIM, h_, h_, nullptr, nullptr, SEQ, DIM, DIM, 0);
        ln_split_kernel<<<SEQ, 256>>>(h_, ln2_g + i * DIM, ln2_b + i * DIM, aH, aL);
        run_mma(aH, aL, f1H + (size_t)i * MLPD * DIM, f1L + (size_t)i * MLPD * DIM,
                fc1_b + i * MLPD, nullptr, nullptr, mH, mL, SEQ, MLPD, DIM, 1);
        run_mma32(mH, mL, f2H + (size_t)i * DIM * MLPD, f2L + (size_t)i * DIM * MLPD,
                  fc2_b + i * DIM, h_, h_, nullptr, nullptr, SEQ, DIM, MLPD, 0);
    }

    ln_kernel<<<SEQ, 256>>>(h_, lnf_g, lnf_b, (float*)d_out);
}

// round 10
// speedup vs baseline: 1.0373x; 1.0373x over previous
#include <cuda_runtime.h>
#include <cuda_bf16.h>
#include <math.h>
#include <stdint.h>

constexpr int SEQ  = 1576;   // T*N tokens
constexpr int DIM  = 768;
constexpr int NHEAD = 12;
constexpr int HD   = 64;
constexpr int TFR  = 8;      // frames
constexpr int NTOK = 197;    // tokens per frame
constexpr int NPAT = 196;
constexpr int MLPD = 3072;
constexpr int QKVD = 2304;
constexpr float ASCALE = 0.125f;
#define QB 8

// ---------------- scratch (no allocation allowed) ----------------
__device__ float g_emb[1568 * 768];
__device__ float g_h[SEQ * DIM];
__device__ float g_qkv[SEQ * QKVD];
__device__ float g_vmean[NHEAD * TFR * HD];
__device__ unsigned short g_p_hi[1568 * 768],  g_p_lo[1568 * 768];
__device__ unsigned short g_a_hi[SEQ * DIM],   g_a_lo[SEQ * DIM];
__device__ unsigned short g_o_hi[SEQ * DIM],   g_o_lo[SEQ * DIM];
__device__ unsigned short g_m_hi[SEQ * MLPD],  g_m_lo[SEQ * MLPD];
__device__ unsigned short g_wp_hi[DIM * DIM],        g_wp_lo[DIM * DIM];
__device__ unsigned short g_qkvT_hi[12 * QKVD * DIM], g_qkvT_lo[12 * QKVD * DIM];
__device__ unsigned short g_projT_hi[12 * DIM * DIM], g_projT_lo[12 * DIM * DIM];
__device__ unsigned short g_fc1T_hi[12 * MLPD * DIM], g_fc1T_lo[12 * MLPD * DIM];
__device__ unsigned short g_fc2T_hi[12 * DIM * MLPD], g_fc2T_lo[12 * DIM * MLPD];

// ================= helpers =================
__device__ __forceinline__ uint32_t smem_u32(const void* p) {
    uint32_t a;
    asm("{ .reg .u64 t; cvta.to.shared.u64 t, %1; cvt.u32.u64 %0, t; }" : "=r"(a) : "l"(p));
    return a;
}
__device__ __forceinline__ void split1(float v, unsigned short& hi, unsigned short& lo) {
    __nv_bfloat16 h = __float2bfloat16(v);
    __nv_bfloat16 l = __float2bfloat16(v - __bfloat162float(h));
    hi = __bfloat16_as_ushort(h);
    lo = __bfloat16_as_ushort(l);
}

#define LDM4(r, addr) \
    asm volatile("ldmatrix.sync.aligned.m8n8.x4.shared.b16 {%0,%1,%2,%3}, [%4];" \
        : "=r"((r)[0]), "=r"((r)[1]), "=r"((r)[2]), "=r"((r)[3]) : "r"(addr))

#define MMA_BF16(c, a, b0, b1) \
    asm volatile("mma.sync.aligned.m16n8k16.row.col.f32.bf16.bf16.f32 " \
        "{%0,%1,%2,%3}, {%4,%5,%6,%7}, {%8,%9}, {%0,%1,%2,%3};" \
        : "+f"((c)[0]), "+f"((c)[1]), "+f"((c)[2]), "+f"((c)[3]) \
        : "r"((a)[0]), "r"((a)[1]), "r"((a)[2]), "r"((a)[3]), "r"(b0), "r"(b1))

#define CPA16(dst, src, sz) \
    asm volatile("cp.async.cg.shared.global [%0], [%1], 16, %2;" \
        :: "r"(dst), "l"(src), "r"(sz))
#define CPA_COMMIT() asm volatile("cp.async.commit_group;")
#define CPA_WAIT1()  asm volatile("cp.async.wait_group 1;")

// ---------------- transpose + split: fp32 [K,N] -> bf16 hi/lo [N,K] ----------------
__global__ void transpose_split_kernel(const float* __restrict__ in,
        unsigned short* __restrict__ ohi, unsigned short* __restrict__ olo, int K, int N) {
    __shared__ float t[32][33];
    size_t base = (size_t)blockIdx.z * K * N;
    int n0 = blockIdx.x * 32, k0 = blockIdx.y * 32;
    int tx = threadIdx.x, ty = threadIdx.y;
    #pragma unroll
    for (int j = 0; j < 32; j += 8)
        t[ty + j][tx] = in[base + (size_t)(k0 + ty + j) * N + n0 + tx];
    __syncthreads();
    #pragma unroll
    for (int j = 0; j < 32; j += 8) {
        unsigned short hi, lo;
        split1(t[tx][ty + j], hi, lo);
        size_t o = base + (size_t)(n0 + ty + j) * K + k0 + tx;
        ohi[o] = hi; olo[o] = lo;
    }
}

// ---------------- elementwise split ----------------
__global__ void split_kernel(const float* __restrict__ in,
        unsigned short* __restrict__ hi, unsigned short* __restrict__ lo, int n) {
    int i = blockIdx.x * blockDim.x + threadIdx.x;
    if (i >= n) return;
    split1(in[i], hi[i], lo[i]);
}

// ===================================================================================
// bf16x3 MMA GEMM, cp.async 3-stage pipeline, CTA tile 64x128, 256 threads, 2 CTA/SM.
// MMA issue reordered: 3 passes (hh, hl, lh) over 4 independent accumulators each,
// so consecutive MMAs are independent (dependency distance 4). Bit-identical result.
// ===================================================================================
constexpr int RS = 80;
constexpr int NSTG = 3;
constexpr int AL_OFF = 64 * RS;
constexpr int BH_OFF = 2 * 64 * RS;
constexpr int BL_OFF = BH_OFF + 128 * RS;
constexpr int STG    = BH_OFF + 2 * 128 * RS;   // 30720

__device__ __forceinline__ void load_stage(uint32_t sb,
        const unsigned short* __restrict__ Ahi, const unsigned short* __restrict__ Alo,
        const unsigned short* __restrict__ Bhi, const unsigned short* __restrict__ Blo,
        int row0, int col0, int K, int k0, int M, int tid) {
    int r = tid >> 2, ch = tid & 3;
    uint32_t doff = (uint32_t)(r * RS + ch * 16);
    size_t asrc = (size_t)(row0 + r) * K + k0 + ch * 8;
    int av = (row0 + r < M) ? 16 : 0;
    CPA16(sb + doff, Ahi + asrc, av);
    CPA16(sb + AL_OFF + doff, Alo + asrc, av);
    size_t b0 = (size_t)(col0 + r) * K + k0 + ch * 8;
    size_t b1 = (size_t)(col0 + 64 + r) * K + k0 + ch * 8;
    CPA16(sb + BH_OFF + doff, Bhi + b0, 16);
    CPA16(sb + BH_OFF + doff + 64 * RS, Bhi + b1, 16);
    CPA16(sb + BL_OFF + doff, Blo + b0, 16);
    CPA16(sb + BL_OFF + doff + 64 * RS, Blo + b1, 16);
    CPA_COMMIT();
}

__global__ void __launch_bounds__(256, 2) mma_gemm(
        const unsigned short* __restrict__ Ahi, const unsigned short* __restrict__ Alo,
        const unsigned short* __restrict__ Bhi, const unsigned short* __restrict__ Blo,
        const float* __restrict__ bias, const float* __restrict__ res,
        float* __restrict__ C, unsigned short* __restrict__ Chi,
        unsigned short* __restrict__ Clo,
        int M, int N, int K, int act) {
    extern __shared__ __align__(128) char sm[];
    const int tid = threadIdx.x;
    const int lane = tid & 31, wid = tid >> 5;
    const int wm = wid & 1, wn = wid >> 1;
    const int row0 = blockIdx.y * 64, col0 = blockIdx.x * 128;
    const uint32_t smb = smem_u32(sm);

    const int a_row = ((lane >> 3) & 1) * 8 + (lane & 7);
    const int a_kb  = (lane >> 4) * 16;
    const int b_row = (lane >> 4) * 8 + (lane & 7);
    const int b_kb  = ((lane >> 3) & 1) * 16;

    float c[2][4][4];
    #pragma unroll
    for (int i = 0; i < 2; i++)
        #pragma unroll
        for (int j = 0; j < 4; j++)
            #pragma unroll
            for (int k = 0; k < 4; k++) c[i][j][k] = 0.f;

    const int nk = K >> 5;
    load_stage(smb, Ahi, Alo, Bhi, Blo, row0, col0, K, 0, M, tid);
    load_stage(smb + STG, Ahi, Alo, Bhi, Blo, row0, col0, K, 32, M, tid);

    int buf = 0;
    for (int it = 0; it < nk; it++) {
        CPA_WAIT1();
        __syncthreads();
        if (it + 2 < nk) {
            int nb = buf + 2; if (nb >= NSTG) nb -= NSTG;
            load_stage(smb + (uint32_t)nb * STG, Ahi, Alo, Bhi, Blo,
                       row0, col0, K, (it + 2) << 5, M, tid);
        }
        uint32_t sb = smb + (uint32_t)buf * STG;
        #pragma unroll
        for (int kk = 0; kk < 2; kk++) {
            uint32_t bh[8], bl[8];
            #pragma unroll
            for (int nip = 0; nip < 2; nip++) {
                uint32_t baddr = sb + BH_OFF + (wn * 32 + nip * 16 + b_row) * RS + b_kb + kk * 32;
                LDM4(&bh[nip * 4], baddr);
                LDM4(&bl[nip * 4], baddr + (BL_OFF - BH_OFF));
            }
            #pragma unroll
            for (int mi = 0; mi < 2; mi++) {
                uint32_t ah[4], al[4];
                uint32_t aaddr = sb + (wm * 32 + mi * 16 + a_row) * RS + a_kb + kk * 32;
                LDM4(ah, aaddr);
                LDM4(al, aaddr + AL_OFF);
                // pass 1: ah * bh  (4 independent accumulators back-to-back)
                #pragma unroll
                for (int ni = 0; ni < 4; ni++) {
                    int bi = (ni >> 1) * 4 + (ni & 1) * 2;
                    MMA_BF16(c[mi][ni], ah, bh[bi], bh[bi + 1]);
                }
                // pass 2: ah * bl
                #pragma unroll
                for (int ni = 0; ni < 4; ni++) {
                    int bi = (ni >> 1) * 4 + (ni & 1) * 2;
                    MMA_BF16(c[mi][ni], ah, bl[bi], bl[bi + 1]);
                }
                // pass 3: al * bh
                #pragma unroll
                for (int ni = 0; ni < 4; ni++) {
                    int bi = (ni >> 1) * 4 + (ni & 1) * 2;
                    MMA_BF16(c[mi][ni], al, bh[bi], bh[bi + 1]);
                }
            }
        }
        buf++; if (buf >= NSTG) buf = 0;
    }

    // ---- epilogue ----
    const int g = lane >> 2, t = lane & 3;
    #pragma unroll
    for (int mi = 0; mi < 2; mi++) {
        #pragma unroll
        for (int ni = 0; ni < 4; ni++) {
            int col = col0 + wn * 32 + ni * 8 + t * 2;
            float2 bb = bias ? *(const float2*)(bias + col) : make_float2(0.f, 0.f);
            #pragma unroll
            for (int half = 0; half < 2; half++) {
                int gm = row0 + wm * 32 + mi * 16 + g + half * 8;
                if (gm >= M) continue;
                float v0 = c[mi][ni][half * 2 + 0] + bb.x;
                float v1 = c[mi][ni][half * 2 + 1] + bb.y;
                if (act) {
                    v0 = 0.5f * v0 * (1.f + erff(v0 * 0.70710678118f));
                    v1 = 0.5f * v1 * (1.f + erff(v1 * 0.70710678118f));
                }
                if (res) {
                    float2 rv = *(const float2*)(res + (size_t)gm * N + col);
                    v0 += rv.x; v1 += rv.y;
                }
                size_t o = (size_t)gm * N + col;
                if (Chi) {
                    unsigned short h0, l0, h1, l1;
                    split1(v0, h0, l0);
                    split1(v1, h1, l1);
                    *(uint32_t*)(Chi + o) = (uint32_t)h0 | ((uint32_t)h1 << 16);
                    *(uint32_t*)(Clo + o) = (uint32_t)l0 | ((uint32_t)l1 << 16);
                } else {
                    *(float2*)(C + o) = make_float2(v0, v1);
                }
            }
        }
    }
}

// ---------------- patch extraction -> bf16 hi/lo ----------------
__global__ void patch_kernel(const float* __restrict__ x,
        unsigned short* __restrict__ Phi, unsigned short* __restrict__ Plo) {
    int idx = blockIdx.x * blockDim.x + threadIdx.x;
    if (idx >= 1568 * 768) return;
    int m = idx / 768, kcol = idx % 768;
    int t = m / 196, n = m % 196;
    int hp = n / 14, wp = n % 14;
    int c = kcol / 256, rem = kcol % 256;
    int ii = rem / 16, jj = rem % 16;
    float v = x[((t * 3 + c) * 224 + hp * 16 + ii) * 224 + wp * 16 + jj];
    split1(v, Phi[idx], Plo[idx]);
}

// ---------------- assemble h ----------------
__global__ void assemble_kernel(const float* __restrict__ emb, const float* __restrict__ cls,
                                const float* __restrict__ pos, float* __restrict__ h) {
    int idx = blockIdx.x * blockDim.x + threadIdx.x;
    if (idx >= SEQ * DIM) return;
    int m = idx / DIM, dd = idx % DIM;
    int t = m / NTOK, r = m % NTOK;
    float v;
    if (r == 0) {
        v = cls[dd] + pos[dd];
    } else {
        int pp = r - 1;
        int f = pp * DIM + dd;
        int n = f % NPAT, dc = f / NPAT;
        v = emb[(t * NPAT + n) * DIM + dc] + pos[(1 + pp) * DIM + dd];
    }
    h[idx] = v;
}

// ---------------- block reduction ----------------
__device__ __forceinline__ float block_sum256(float v, float* sh) {
    #pragma unroll
    for (int o = 16; o; o >>= 1) v += __shfl_xor_sync(0xffffffffu, v, o);
    if ((threadIdx.x & 31) == 0) sh[threadIdx.x >> 5] = v;
    __syncthreads();
    float t = 0.f;
    #pragma unroll
    for (int i = 0; i < 8; i++) t += sh[i];
    __syncthreads();
    return t;
}

// ---------------- LayerNorm -> bf16 hi/lo ----------------
__global__ void ln_split_kernel(const float* __restrict__ x, const float* __restrict__ g,
        const float* __restrict__ b, unsigned short* __restrict__ yhi,
        unsigned short* __restrict__ ylo) {
    __shared__ float sh[8];
    int row = blockIdx.x, tid = threadIdx.x;
    const float* xr = x + (size_t)row * DIM;
    float v0 = xr[tid], v1 = xr[tid + 256], v2 = xr[tid + 512];
    float mean = block_sum256(v0 + v1 + v2, sh) * (1.f / DIM);
    float d0 = v0 - mean, d1 = v1 - mean, d2 = v2 - mean;
    float var = block_sum256(d0 * d0 + d1 * d1 + d2 * d2, sh) * (1.f / DIM);
    float inv = rsqrtf(var + 1e-5f);
    size_t o = (size_t)row * DIM + tid;
    float y0 = d0 * inv * g[tid]       + b[tid];
    float y1 = d1 * inv * g[tid + 256] + b[tid + 256];
    float y2 = d2 * inv * g[tid + 512] + b[tid + 512];
    split1(y0, yhi[o],       ylo[o]);
    split1(y1, yhi[o + 256], ylo[o + 256]);
    split1(y2, yhi[o + 512], ylo[o + 512]);
}

// ---------------- final LayerNorm (fp32 out) ----------------
__global__ void ln_kernel(const float* __restrict__ x, const float* __restrict__ g,
                          const float* __restrict__ b, float* __restrict__ y) {
    __shared__ float sh[8];
    int row = blockIdx.x, tid = threadIdx.x;
    const float* xr = x + (size_t)row * DIM;
    float v0 = xr[tid], v1 = xr[tid + 256], v2 = xr[tid + 512];
    float mean = block_sum256(v0 + v1 + v2, sh) * (1.f / DIM);
    float d0 = v0 - mean, d1 = v1 - mean, d2 = v2 - mean;
    float var = block_sum256(d0 * d0 + d1 * d1 + d2 * d2, sh) * (1.f / DIM);
    float inv = rsqrtf(var + 1e-5f);
    float* yr = y + (size_t)row * DIM;
    yr[tid]       = d0 * inv * g[tid]       + b[tid];
    yr[tid + 256] = d1 * inv * g[tid + 256] + b[tid + 256];
    yr[tid + 512] = d2 * inv * g[tid + 512] + b[tid + 512];
}

// ---------------- temporal v-mean ----------------
__global__ void vmean_kernel(const float* __restrict__ qkv, float* __restrict__ vmean) {
    int ht = blockIdx.x;
    int t = ht % TFR, h = ht / TFR;
    int d = threadIdx.x;
    float s = 0.f;
    for (int n = 0; n < NTOK; n++)
        s += qkv[(size_t)(t * NTOK + n) * QKVD + 2 * DIM + h * HD + d];
    vmean[ht * HD + d] = s * (1.f / NTOK);
}

// ---------------- attention (QB=8, 4-key register-blocked scores) ----------------
__global__ void attn_kernel(const float* __restrict__ qkv, const float* __restrict__ vmean,
        unsigned short* __restrict__ ohi, unsigned short* __restrict__ olo,
        int keyLen, int keyLenP, int numSeg) {
    extern __shared__ float smf[];
    float* qs  = smf;                       // QB*HD
    float* sc  = smf + QB * HD;             // QB*keyLenP
    float* red = sc + QB * keyLenP;         // 4*QB*HD
    __shared__ float wsum[QB];
    int tid = threadIdx.x;
    int hseg = blockIdx.y;
    int h = hseg / numSeg, seg = hseg % numSeg;
    int base = seg * keyLen;
    int q0 = blockIdx.x * QB;
    int nq = min(QB, keyLen - q0);

    for (int i = tid; i < QB * HD; i += 256) {
        int qi = i / HD, d = i % HD;
        qs[i] = (qi < nq) ? qkv[(size_t)(base + q0 + qi) * QKVD + h * HD + d] : 0.f;
    }
    __syncthreads();

    const int nkb = (keyLen + 3) >> 2;
    for (int kb = tid; kb < nkb; kb += 256) {
        int kk = kb << 2;
        float acc[QB][4];
        #pragma unroll
        for (int qi = 0; qi < QB; qi++)
            #pragma unroll
            for (int c = 0; c < 4; c++) acc[qi][c] = 0.f;
        const float* kbase0 = qkv + (size_t)(base + kk) * QKVD + DIM + h * HD;
        int v1 = (kk + 1 < keyLen) ? 1 : 0;
        int v2 = (kk + 2 < keyLen) ? 2 : 0;
        int v3 = (kk + 3 < keyLen) ? 3 : 0;
        #pragma unroll 4
        for (int j = 0; j < 16; j++) {
            float4 k0 = *(const float4*)(kbase0 + (size_t)0  * QKVD + j * 4);
            float4 k1 = *(const float4*)(kbase0 + (size_t)v1 * QKVD + j * 4);
            float4 k2 = *(const float4*)(kbase0 + (size_t)v2 * QKVD + j * 4);
            float4 k3 = *(const float4*)(kbase0 + (size_t)v3 * QKVD + j * 4);
            #pragma unroll
            for (int qi = 0; qi < QB; qi++) {
                float4 q = *(const float4*)(qs + qi * HD + j * 4);
                acc[qi][0] += q.x * k0.x + q.y * k0.y + q.z * k0.z + q.w * k0.w;
                acc[qi][1] += q.x * k1.x + q.y * k1.y + q.z * k1.z + q.w * k1.w;
                acc[qi][2] += q.x * k2.x + q.y * k2.y + q.z * k2.z + q.w * k2.w;
                acc[qi][3] += q.x * k3.x + q.y * k3.y + q.z * k3.z + q.w * k3.w;
            }
        }
        #pragma unroll
        for (int qi = 0; qi < QB; qi++) {
            float* dst = sc + qi * keyLenP + kk;
            if (kk + 3 < keyLen) {
                *(float4*)dst = make_float4(acc[qi][0] * ASCALE, acc[qi][1] * ASCALE,
                                            acc[qi][2] * ASCALE, acc[qi][3] * ASCALE);
            } else {
                for (int c = 0; c < 4; c++)
                    if (kk + c < keyLen) dst[c] = acc[qi][c] * ASCALE;
            }
        }
    }
    __syncthreads();

    int w = tid >> 5, lane = tid & 31;
    if (w < nq) {
        float mx = -1e30f;
        for (int kk = lane; kk < keyLen; kk += 32) mx = fmaxf(mx, sc[w * keyLenP + kk]);
        #pragma unroll
        for (int off = 16; off; off >>= 1) mx = fmaxf(mx, __shfl_xor_sync(0xffffffffu, mx, off));
        float sum = 0.f;
        for (int kk = lane; kk < keyLen; kk += 32) {
            float e = __expf(sc[w * keyLenP + kk] - mx);
            sc[w * keyLenP + kk] = e;
            sum += e;
        }
        #pragma unroll
        for (int off = 16; off; off >>= 1) sum += __shfl_xor_sync(0xffffffffu, sum, off);
        if (lane == 0) wsum[w] = sum;
    }
    __syncthreads();

    int d = tid & 63, part = tid >> 6;
    float acc[QB];
    #pragma unroll
    for (int qi = 0; qi < QB; qi++) acc[qi] = 0.f;
    for (int kk = part; kk < keyLen; kk += 4) {
        float v = qkv[(size_t)(base + kk) * QKVD + 2 * DIM + h * HD + d];
        #pragma unroll
        for (int qi = 0; qi < QB; qi++)
            if (qi < nq) acc[qi] += sc[qi * keyLenP + kk] * v;
    }
    #pragma unroll
    for (int qi = 0; qi < QB; qi++)
        red[(part * QB + qi) * HD + d] = acc[qi];
    __syncthreads();
    if (part == 0) {
        for (int qi = 0; qi < nq; qi++) {
            float s = red[qi * HD + d] + red[(QB + qi) * HD + d]
                    + red[(2 * QB + qi) * HD + d] + red[(3 * QB + qi) * HD + d];
            s /= wsum[qi];
            if (vmean) s += vmean[hseg * HD + d];
            size_t o = (size_t)(base + q0 + qi) * DIM + h * HD + d;
            split1(s, ohi[o], olo[o]);
        }
    }
}

// ---------------- host ----------------
static void run_mma(const unsigned short* Ahi, const unsigned short* Alo,
                    const unsigned short* Bhi, const unsigned short* Blo,
                    const float* bias, const float* res, float* C,
                    unsigned short* Chi, unsigned short* Clo,
                    int M, int N, int K, int act) {
    dim3 grid(N / 128, (M + 63) / 64);
    mma_gemm<<<grid, 256, NSTG * STG>>>(Ahi, Alo, Bhi, Blo, bias, res, C, Chi, Clo, M, N, K, act);
}

extern "C" void kernel_launch(void* const* d_in, const int* in_sizes, int n_in,
                              void* d_out, int out_size) {
    const float* x       = (const float*)d_in[0];
    const float* W_patch = (const float*)d_in[1];
    const float* b_patch = (const float*)d_in[2];
    const float* cls     = (const float*)d_in[3];
    const float* pos     = (const float*)d_in[4];
    const float* ln1_g   = (const float*)d_in[5];
    const float* ln1_b   = (const float*)d_in[6];
    const float* qkv_w   = (const float*)d_in[7];
    const float* qkv_b   = (const float*)d_in[8];
    const float* proj_w  = (const float*)d_in[9];
    const float* proj_b  = (const float*)d_in[10];
    const float* ln2_g   = (const float*)d_in[11];
    const float* ln2_b   = (const float*)d_in[12];
    const float* fc1_w   = (const float*)d_in[13];
    const float* fc1_b   = (const float*)d_in[14];
    const float* fc2_w   = (const float*)d_in[15];
    const float* fc2_b   = (const float*)d_in[16];
    const float* lnf_g   = (const float*)d_in[17];
    const float* lnf_b   = (const float*)d_in[18];

    float *emb_, *h_, *qkv_, *vm_;
    unsigned short *pH, *pL, *aH, *aL, *oH, *oL, *mH, *mL;
    unsigned short *wpH, *wpL, *qkH, *qkL, *prH, *prL, *f1H, *f1L, *f2H, *f2L;
    cudaGetSymbolAddress((void**)&emb_, g_emb);
    cudaGetSymbolAddress((void**)&h_,   g_h);
    cudaGetSymbolAddress((void**)&qkv_, g_qkv);
    cudaGetSymbolAddress((void**)&vm_,  g_vmean);
    cudaGetSymbolAddress((void**)&pH, g_p_hi);   cudaGetSymbolAddress((void**)&pL, g_p_lo);
    cudaGetSymbolAddress((void**)&aH, g_a_hi);   cudaGetSymbolAddress((void**)&aL, g_a_lo);
    cudaGetSymbolAddress((void**)&oH, g_o_hi);   cudaGetSymbolAddress((void**)&oL, g_o_lo);
    cudaGetSymbolAddress((void**)&mH, g_m_hi);   cudaGetSymbolAddress((void**)&mL, g_m_lo);
    cudaGetSymbolAddress((void**)&wpH, g_wp_hi); cudaGetSymbolAddress((void**)&wpL, g_wp_lo);
    cudaGetSymbolAddress((void**)&qkH, g_qkvT_hi); cudaGetSymbolAddress((void**)&qkL, g_qkvT_lo);
    cudaGetSymbolAddress((void**)&prH, g_projT_hi); cudaGetSymbolAddress((void**)&prL, g_projT_lo);
    cudaGetSymbolAddress((void**)&f1H, g_fc1T_hi); cudaGetSymbolAddress((void**)&f1L, g_fc1T_lo);
    cudaGetSymbolAddress((void**)&f2H, g_fc2T_hi); cudaGetSymbolAddress((void**)&f2L, g_fc2T_lo);

    cudaFuncSetAttribute(mma_gemm, cudaFuncAttributeMaxDynamicSharedMemorySize, NSTG * STG);

    size_t smem_joint = (size_t)(QB * HD + QB * SEQ  + 4 * QB * HD) * sizeof(float);
    size_t smem_sp    = (size_t)(QB * HD + QB * 200  + 4 * QB * HD) * sizeof(float);
    cudaFuncSetAttribute(attn_kernel, cudaFuncAttributeMaxDynamicSharedMemorySize, (int)smem_joint);

    patch_kernel<<<(1568 * 768 + 255) / 256, 256>>>(x, pH, pL);                       // 0
    split_kernel<<<(DIM * DIM + 255) / 256, 256>>>(W_patch, wpH, wpL, DIM * DIM);     // 1
    dim3 tb(32, 8);
    transpose_split_kernel<<<dim3(QKVD / 32, DIM / 32, 12), tb>>>(qkv_w, qkH, qkL, DIM, QKVD); // 2
    run_mma(pH, pL, wpH, wpL, b_patch, nullptr, emb_, nullptr, nullptr, 1568, 768, 768, 0);    // 3 <- profiled
    transpose_split_kernel<<<dim3(DIM / 32,  DIM / 32, 12), tb>>>(proj_w, prH, prL, DIM, DIM);
    transpose_split_kernel<<<dim3(MLPD / 32, DIM / 32, 12), tb>>>(fc1_w,  f1H, f1L, DIM, MLPD);
    transpose_split_kernel<<<dim3(DIM / 32, MLPD / 32, 12), tb>>>(fc2_w,  f2H, f2L, MLPD, DIM);
    assemble_kernel<<<(SEQ * DIM + 255) / 256, 256>>>(emb_, cls, pos, h_);

    for (int i = 0; i < 12; i++) {
        ln_split_kernel<<<SEQ, 256>>>(h_, ln1_g + i * DIM, ln1_b + i * DIM, aH, aL);
        run_mma(aH, aL, qkH + (size_t)i * QKVD * DIM, qkL + (size_t)i * QKVD * DIM,
                qkv_b + i * QKVD, nullptr, qkv_, nullptr, nullptr, SEQ, QKVD, DIM, 0);
        if ((i & 1) == 0) {
            vmean_kernel<<<NHEAD * TFR, HD>>>(qkv_, vm_);
            dim3 g((NTOK + QB - 1) / QB, NHEAD * TFR);
            attn_kernel<<<g, 256, smem_sp>>>(qkv_, vm_, oH, oL, NTOK, 200, TFR);
        } else {
            dim3 g((SEQ + QB - 1) / QB, NHEAD);
            attn_kernel<<<g, 256, smem_joint>>>(qkv_, nullptr, oH, oL, SEQ, SEQ, 1);
        }
        run_mma(oH, oL, prH + (size_t)i * DIM * DIM, prL + (size_t)i * DIM * DIM,
                proj_b + i * DIM, h_, h_, nullptr, nullptr, SEQ, DIM, DIM, 0);
        ln_split_kernel<<<SEQ, 256>>>(h_, ln2_g + i * DIM, ln2_b + i * DIM, aH, aL);
        run_mma(aH, aL, f1H + (size_t)i * MLPD * DIM, f1L + (size_t)i * MLPD * DIM,
                fc1_b + i * MLPD, nullptr, nullptr, mH, mL, SEQ, MLPD, DIM, 1);
        run_mma(mH, mL, f2H + (size_t)i * DIM * MLPD, f2L + (size_t)i * DIM * MLPD,
                fc2_b + i * DIM, h_, h_, nullptr, nullptr, SEQ, DIM, MLPD, 0);
    }

    ln_kernel<<<SEQ, 256>>>(h_, lnf_g, lnf_b, (float*)d_out);
}

// round 11
// speedup vs baseline: 1.3377x; 1.2896x over previous
#include <cuda_runtime.h>
#include <cuda_bf16.h>
#include <math.h>
#include <stdint.h>

constexpr int SEQ  = 1576;   // T*N tokens
constexpr int DIM  = 768;
constexpr int NHEAD = 12;
constexpr int HD   = 64;
constexpr int TFR  = 8;      // frames
constexpr int NTOK = 197;    // tokens per frame
constexpr int NPAT = 196;
constexpr int MLPD = 3072;
constexpr int QKVD = 2304;
constexpr float ASCALE = 0.125f;
#define QB 8

// ---------------- scratch (no allocation allowed) ----------------
__device__ float g_emb[1568 * 768];
__device__ float g_h[SEQ * DIM];
__device__ float g_qkv[SEQ * QKVD];
__device__ float g_vmean[NHEAD * TFR * HD];
__device__ unsigned short g_p_hi[1568 * 768],  g_p_lo[1568 * 768];
__device__ unsigned short g_a_hi[SEQ * DIM],   g_a_lo[SEQ * DIM];
__device__ unsigned short g_o_hi[SEQ * DIM],   g_o_lo[SEQ * DIM];
__device__ unsigned short g_m_hi[SEQ * MLPD],  g_m_lo[SEQ * MLPD];
__device__ unsigned short g_wp_hi[DIM * DIM],        g_wp_lo[DIM * DIM];
__device__ unsigned short g_qkvT_hi[12 * QKVD * DIM], g_qkvT_lo[12 * QKVD * DIM];
__device__ unsigned short g_projT_hi[12 * DIM * DIM], g_projT_lo[12 * DIM * DIM];
__device__ unsigned short g_fc1T_hi[12 * MLPD * DIM], g_fc1T_lo[12 * MLPD * DIM];
__device__ unsigned short g_fc2T_hi[12 * DIM * MLPD], g_fc2T_lo[12 * DIM * MLPD];

// ================= helpers =================
__device__ __forceinline__ uint32_t smem_u32(const void* p) {
    uint32_t a;
    asm("{ .reg .u64 t; cvta.to.shared.u64 t, %1; cvt.u32.u64 %0, t; }" : "=r"(a) : "l"(p));
    return a;
}
__device__ __forceinline__ void split1(float v, unsigned short& hi, unsigned short& lo) {
    __nv_bfloat16 h = __float2bfloat16(v);
    __nv_bfloat16 l = __float2bfloat16(v - __bfloat162float(h));
    hi = __bfloat16_as_ushort(h);
    lo = __bfloat16_as_ushort(l);
}

#define LDM4(r, addr) \
    asm volatile("ldmatrix.sync.aligned.m8n8.x4.shared.b16 {%0,%1,%2,%3}, [%4];" \
        : "=r"((r)[0]), "=r"((r)[1]), "=r"((r)[2]), "=r"((r)[3]) : "r"(addr))

#define MMA_BF16(c, a, b0, b1) \
    asm volatile("mma.sync.aligned.m16n8k16.row.col.f32.bf16.bf16.f32 " \
        "{%0,%1,%2,%3}, {%4,%5,%6,%7}, {%8,%9}, {%0,%1,%2,%3};" \
        : "+f"((c)[0]), "+f"((c)[1]), "+f"((c)[2]), "+f"((c)[3]) \
        : "r"((a)[0]), "r"((a)[1]), "r"((a)[2]), "r"((a)[3]), "r"(b0), "r"(b1))

#define CPA16(dst, src, sz) \
    asm volatile("cp.async.cg.shared.global [%0], [%1], 16, %2;" \
        :: "r"(dst), "l"(src), "r"(sz))
#define CPA_COMMIT() asm volatile("cp.async.commit_group;")
#define CPA_WAIT1()  asm volatile("cp.async.wait_group 1;")

// ---------------- transpose + split: fp32 [K,N] -> bf16 hi/lo [N,K] ----------------
__global__ void transpose_split_kernel(const float* __restrict__ in,
        unsigned short* __restrict__ ohi, unsigned short* __restrict__ olo, int K, int N) {
    __shared__ float t[32][33];
    size_t base = (size_t)blockIdx.z * K * N;
    int n0 = blockIdx.x * 32, k0 = blockIdx.y * 32;
    int tx = threadIdx.x, ty = threadIdx.y;
    #pragma unroll
    for (int j = 0; j < 32; j += 8)
        t[ty + j][tx] = in[base + (size_t)(k0 + ty + j) * N + n0 + tx];
    __syncthreads();
    #pragma unroll
    for (int j = 0; j < 32; j += 8) {
        unsigned short hi, lo;
        split1(t[tx][ty + j], hi, lo);
        size_t o = base + (size_t)(n0 + ty + j) * K + k0 + tx;
        ohi[o] = hi; olo[o] = lo;
    }
}

// ---------------- elementwise split ----------------
__global__ void split_kernel(const float* __restrict__ in,
        unsigned short* __restrict__ hi, unsigned short* __restrict__ lo, int n) {
    int i = blockIdx.x * blockDim.x + threadIdx.x;
    if (i >= n) return;
    split1(in[i], hi[i], lo[i]);
}

// ===================================================================================
// bf16x3 MMA GEMM, cp.async 3-stage pipeline, CTA tile 64x128, 256 threads, 2 CTA/SM.
// (exact round-8 best configuration)
// ===================================================================================
constexpr int RS = 80;
constexpr int NSTG = 3;
constexpr int AL_OFF = 64 * RS;
constexpr int BH_OFF = 2 * 64 * RS;
constexpr int BL_OFF = BH_OFF + 128 * RS;
constexpr int STG    = BH_OFF + 2 * 128 * RS;   // 30720

__device__ __forceinline__ void load_stage(uint32_t sb,
        const unsigned short* __restrict__ Ahi, const unsigned short* __restrict__ Alo,
        const unsigned short* __restrict__ Bhi, const unsigned short* __restrict__ Blo,
        int row0, int col0, int K, int k0, int M, int tid) {
    int r = tid >> 2, ch = tid & 3;
    uint32_t doff = (uint32_t)(r * RS + ch * 16);
    size_t asrc = (size_t)(row0 + r) * K + k0 + ch * 8;
    int av = (row0 + r < M) ? 16 : 0;
    CPA16(sb + doff, Ahi + asrc, av);
    CPA16(sb + AL_OFF + doff, Alo + asrc, av);
    size_t b0 = (size_t)(col0 + r) * K + k0 + ch * 8;
    size_t b1 = (size_t)(col0 + 64 + r) * K + k0 + ch * 8;
    CPA16(sb + BH_OFF + doff, Bhi + b0, 16);
    CPA16(sb + BH_OFF + doff + 64 * RS, Bhi + b1, 16);
    CPA16(sb + BL_OFF + doff, Blo + b0, 16);
    CPA16(sb + BL_OFF + doff + 64 * RS, Blo + b1, 16);
    CPA_COMMIT();
}

__global__ void __launch_bounds__(256, 2) mma_gemm(
        const unsigned short* __restrict__ Ahi, const unsigned short* __restrict__ Alo,
        const unsigned short* __restrict__ Bhi, const unsigned short* __restrict__ Blo,
        const float* __restrict__ bias, const float* __restrict__ res,
        float* __restrict__ C, unsigned short* __restrict__ Chi,
        unsigned short* __restrict__ Clo,
        int M, int N, int K, int act) {
    extern __shared__ __align__(128) char sm[];
    const int tid = threadIdx.x;
    const int lane = tid & 31, wid = tid >> 5;
    const int wm = wid & 1, wn = wid >> 1;
    const int row0 = blockIdx.y * 64, col0 = blockIdx.x * 128;
    const uint32_t smb = smem_u32(sm);

    const int a_row = ((lane >> 3) & 1) * 8 + (lane & 7);
    const int a_kb  = (lane >> 4) * 16;
    const int b_row = (lane >> 4) * 8 + (lane & 7);
    const int b_kb  = ((lane >> 3) & 1) * 16;

    float c[2][4][4];
    #pragma unroll
    for (int i = 0; i < 2; i++)
        #pragma unroll
        for (int j = 0; j < 4; j++)
            #pragma unroll
            for (int k = 0; k < 4; k++) c[i][j][k] = 0.f;

    const int nk = K >> 5;
    load_stage(smb, Ahi, Alo, Bhi, Blo, row0, col0, K, 0, M, tid);
    load_stage(smb + STG, Ahi, Alo, Bhi, Blo, row0, col0, K, 32, M, tid);

    int buf = 0;
    for (int it = 0; it < nk; it++) {
        CPA_WAIT1();
        __syncthreads();
        if (it + 2 < nk) {
            int nb = buf + 2; if (nb >= NSTG) nb -= NSTG;
            load_stage(smb + (uint32_t)nb * STG, Ahi, Alo, Bhi, Blo,
                       row0, col0, K, (it + 2) << 5, M, tid);
        }
        uint32_t sb = smb + (uint32_t)buf * STG;
        #pragma unroll
        for (int kk = 0; kk < 2; kk++) {
            uint32_t bh[8], bl[8];
            #pragma unroll
            for (int nip = 0; nip < 2; nip++) {
                uint32_t baddr = sb + BH_OFF + (wn * 32 + nip * 16 + b_row) * RS + b_kb + kk * 32;
                LDM4(&bh[nip * 4], baddr);
                LDM4(&bl[nip * 4], baddr + (BL_OFF - BH_OFF));
            }
            #pragma unroll
            for (int mi = 0; mi < 2; mi++) {
                uint32_t ah[4], al[4];
                uint32_t aaddr = sb + (wm * 32 + mi * 16 + a_row) * RS + a_kb + kk * 32;
                LDM4(ah, aaddr);
                LDM4(al, aaddr + AL_OFF);
                #pragma unroll
                for (int ni = 0; ni < 4; ni++) {
                    uint32_t b0h = bh[(ni >> 1) * 4 + (ni & 1) * 2];
                    uint32_t b1h = bh[(ni >> 1) * 4 + (ni & 1) * 2 + 1];
                    uint32_t b0l = bl[(ni >> 1) * 4 + (ni & 1) * 2];
                    uint32_t b1l = bl[(ni >> 1) * 4 + (ni & 1) * 2 + 1];
                    MMA_BF16(c[mi][ni], ah, b0h, b1h);
                    MMA_BF16(c[mi][ni], ah, b0l, b1l);
                    MMA_BF16(c[mi][ni], al, b0h, b1h);
                }
            }
        }
        buf++; if (buf >= NSTG) buf = 0;
    }

    // ---- epilogue ----
    const int g = lane >> 2, t = lane & 3;
    #pragma unroll
    for (int mi = 0; mi < 2; mi++) {
        #pragma unroll
        for (int ni = 0; ni < 4; ni++) {
            int col = col0 + wn * 32 + ni * 8 + t * 2;
            float2 bb = bias ? *(const float2*)(bias + col) : make_float2(0.f, 0.f);
            #pragma unroll
            for (int half = 0; half < 2; half++) {
                int gm = row0 + wm * 32 + mi * 16 + g + half * 8;
                if (gm >= M) continue;
                float v0 = c[mi][ni][half * 2 + 0] + bb.x;
                float v1 = c[mi][ni][half * 2 + 1] + bb.y;
                if (act) {
                    v0 = 0.5f * v0 * (1.f + erff(v0 * 0.70710678118f));
                    v1 = 0.5f * v1 * (1.f + erff(v1 * 0.70710678118f));
                }
                if (res) {
                    float2 rv = *(const float2*)(res + (size_t)gm * N + col);
                    v0 += rv.x; v1 += rv.y;
                }
                size_t o = (size_t)gm * N + col;
                if (Chi) {
                    unsigned short h0, l0, h1, l1;
                    split1(v0, h0, l0);
                    split1(v1, h1, l1);
                    *(uint32_t*)(Chi + o) = (uint32_t)h0 | ((uint32_t)h1 << 16);
                    *(uint32_t*)(Clo + o) = (uint32_t)l0 | ((uint32_t)l1 << 16);
                } else {
                    *(float2*)(C + o) = make_float2(v0, v1);
                }
            }
        }
    }
}

// ---------------- patch extraction -> bf16 hi/lo ----------------
__global__ void patch_kernel(const float* __restrict__ x,
        unsigned short* __restrict__ Phi, unsigned short* __restrict__ Plo) {
    int idx = blockIdx.x * blockDim.x + threadIdx.x;
    if (idx >= 1568 * 768) return;
    int m = idx / 768, kcol = idx % 768;
    int t = m / 196, n = m % 196;
    int hp = n / 14, wp = n % 14;
    int c = kcol / 256, rem = kcol % 256;
    int ii = rem / 16, jj = rem % 16;
    float v = x[((t * 3 + c) * 224 + hp * 16 + ii) * 224 + wp * 16 + jj];
    split1(v, Phi[idx], Plo[idx]);
}

// ---------------- assemble h ----------------
__global__ void assemble_kernel(const float* __restrict__ emb, const float* __restrict__ cls,
                                const float* __restrict__ pos, float* __restrict__ h) {
    int idx = blockIdx.x * blockDim.x + threadIdx.x;
    if (idx >= SEQ * DIM) return;
    int m = idx / DIM, dd = idx % DIM;
    int t = m / NTOK, r = m % NTOK;
    float v;
    if (r == 0) {
        v = cls[dd] + pos[dd];
    } else {
        int pp = r - 1;
        int f = pp * DIM + dd;
        int n = f % NPAT, dc = f / NPAT;
        v = emb[(t * NPAT + n) * DIM + dc] + pos[(1 + pp) * DIM + dd];
    }
    h[idx] = v;
}

// ---------------- block reduction ----------------
__device__ __forceinline__ float block_sum256(float v, float* sh) {
    #pragma unroll
    for (int o = 16; o; o >>= 1) v += __shfl_xor_sync(0xffffffffu, v, o);
    if ((threadIdx.x & 31) == 0) sh[threadIdx.x >> 5] = v;
    __syncthreads();
    float t = 0.f;
    #pragma unroll
    for (int i = 0; i < 8; i++) t += sh[i];
    __syncthreads();
    return t;
}

// ---------------- LayerNorm -> bf16 hi/lo ----------------
__global__ void ln_split_kernel(const float* __restrict__ x, const float* __restrict__ g,
        const float* __restrict__ b, unsigned short* __restrict__ yhi,
        unsigned short* __restrict__ ylo) {
    __shared__ float sh[8];
    int row = blockIdx.x, tid = threadIdx.x;
    const float* xr = x + (size_t)row * DIM;
    float v0 = xr[tid], v1 = xr[tid + 256], v2 = xr[tid + 512];
    float mean = block_sum256(v0 + v1 + v2, sh) * (1.f / DIM);
    float d0 = v0 - mean, d1 = v1 - mean, d2 = v2 - mean;
    float var = block_sum256(d0 * d0 + d1 * d1 + d2 * d2, sh) * (1.f / DIM);
    float inv = rsqrtf(var + 1e-5f);
    size_t o = (size_t)row * DIM + tid;
    float y0 = d0 * inv * g[tid]       + b[tid];
    float y1 = d1 * inv * g[tid + 256] + b[tid + 256];
    float y2 = d2 * inv * g[tid + 512] + b[tid + 512];
    split1(y0, yhi[o],       ylo[o]);
    split1(y1, yhi[o + 256], ylo[o + 256]);
    split1(y2, yhi[o + 512], ylo[o + 512]);
}

// ---------------- final LayerNorm (fp32 out) ----------------
__global__ void ln_kernel(const float* __restrict__ x, const float* __restrict__ g,
                          const float* __restrict__ b, float* __restrict__ y) {
    __shared__ float sh[8];
    int row = blockIdx.x, tid = threadIdx.x;
    const float* xr = x + (size_t)row * DIM;
    float v0 = xr[tid], v1 = xr[tid + 256], v2 = xr[tid + 512];
    float mean = block_sum256(v0 + v1 + v2, sh) * (1.f / DIM);
    float d0 = v0 - mean, d1 = v1 - mean, d2 = v2 - mean;
    float var = block_sum256(d0 * d0 + d1 * d1 + d2 * d2, sh) * (1.f / DIM);
    float inv = rsqrtf(var + 1e-5f);
    float* yr = y + (size_t)row * DIM;
    yr[tid]       = d0 * inv * g[tid]       + b[tid];
    yr[tid + 256] = d1 * inv * g[tid + 256] + b[tid + 256];
    yr[tid + 512] = d2 * inv * g[tid + 512] + b[tid + 512];
}

// ---------------- temporal v-mean ----------------
__global__ void vmean_kernel(const float* __restrict__ qkv, float* __restrict__ vmean) {
    int ht = blockIdx.x;
    int t = ht % TFR, h = ht / TFR;
    int d = threadIdx.x;
    float s = 0.f;
    for (int n = 0; n < NTOK; n++)
        s += qkv[(size_t)(t * NTOK + n) * QKVD + 2 * DIM + h * HD + d];
    vmean[ht * HD + d] = s * (1.f / NTOK);
}

// ---------------- attention (QB=8, reg-blocked scores, float2 8-part AV) ----------------
__global__ void attn_kernel(const float* __restrict__ qkv, const float* __restrict__ vmean,
        unsigned short* __restrict__ ohi, unsigned short* __restrict__ olo,
        int keyLen, int keyLenP, int numSeg) {
    extern __shared__ float smf[];
    float* qs  = smf;                       // QB*HD
    float* sc  = smf + QB * HD;             // QB*keyLenP
    float* red = sc + QB * keyLenP;         // 8*QB*HD
    __shared__ float wsum[QB];
    int tid = threadIdx.x;
    int hseg = blockIdx.y;
    int h = hseg / numSeg, seg = hseg % numSeg;
    int base = seg * keyLen;
    int q0 = blockIdx.x * QB;
    int nq = min(QB, keyLen - q0);

    for (int i = tid; i < QB * HD; i += 256) {
        int qi = i / HD, d = i % HD;
        qs[i] = (qi < nq) ? qkv[(size_t)(base + q0 + qi) * QKVD + h * HD + d] : 0.f;
    }
    __syncthreads();

    // ---- scores: 4 keys per thread, K fragments in registers ----
    const int nkb = (keyLen + 3) >> 2;
    for (int kb = tid; kb < nkb; kb += 256) {
        int kk = kb << 2;
        float acc[QB][4];
        #pragma unroll
        for (int qi = 0; qi < QB; qi++)
            #pragma unroll
            for (int c = 0; c < 4; c++) acc[qi][c] = 0.f;
        const float* kbase0 = qkv + (size_t)(base + kk) * QKVD + DIM + h * HD;
        int v1 = (kk + 1 < keyLen) ? 1 : 0;
        int v2 = (kk + 2 < keyLen) ? 2 : 0;
        int v3 = (kk + 3 < keyLen) ? 3 : 0;
        #pragma unroll 4
        for (int j = 0; j < 16; j++) {
            float4 k0 = *(const float4*)(kbase0 + (size_t)0  * QKVD + j * 4);
            float4 k1 = *(const float4*)(kbase0 + (size_t)v1 * QKVD + j * 4);
            float4 k2 = *(const float4*)(kbase0 + (size_t)v2 * QKVD + j * 4);
            float4 k3 = *(const float4*)(kbase0 + (size_t)v3 * QKVD + j * 4);
            #pragma unroll
            for (int qi = 0; qi < QB; qi++) {
                float4 q = *(const float4*)(qs + qi * HD + j * 4);
                acc[qi][0] += q.x * k0.x + q.y * k0.y + q.z * k0.z + q.w * k0.w;
                acc[qi][1] += q.x * k1.x + q.y * k1.y + q.z * k1.z + q.w * k1.w;
                acc[qi][2] += q.x * k2.x + q.y * k2.y + q.z * k2.z + q.w * k2.w;
                acc[qi][3] += q.x * k3.x + q.y * k3.y + q.z * k3.z + q.w * k3.w;
            }
        }
        #pragma unroll
        for (int qi = 0; qi < QB; qi++) {
            float* dst = sc + qi * keyLenP + kk;
            if (kk + 3 < keyLen) {
                *(float4*)dst = make_float4(acc[qi][0] * ASCALE, acc[qi][1] * ASCALE,
                                            acc[qi][2] * ASCALE, acc[qi][3] * ASCALE);
            } else {
                for (int c = 0; c < 4; c++)
                    if (kk + c < keyLen) dst[c] = acc[qi][c] * ASCALE;
            }
        }
    }
    __syncthreads();

    // ---- softmax: warp w handles query w ----
    int w = tid >> 5, lane = tid & 31;
    if (w < nq) {
        float mx = -1e30f;
        for (int kk = lane; kk < keyLen; kk += 32) mx = fmaxf(mx, sc[w * keyLenP + kk]);
        #pragma unroll
        for (int off = 16; off; off >>= 1) mx = fmaxf(mx, __shfl_xor_sync(0xffffffffu, mx, off));
        float sum = 0.f;
        for (int kk = lane; kk < keyLen; kk += 32) {
            float e = __expf(sc[w * keyLenP + kk] - mx);
            sc[w * keyLenP + kk] = e;
            sum += e;
        }
        #pragma unroll
        for (int off = 16; off; off >>= 1) sum += __shfl_xor_sync(0xffffffffu, sum, off);
        if (lane == 0) wsum[w] = sum;
    }
    __syncthreads();

    // ---- AV: 8 key-partitions (one per warp), 32 dim-pairs, float2 V loads ----
    {
        int d2 = lane;            // dims 2*d2, 2*d2+1
        int part = w;             // 0..7
        float2 acc[QB];
        #pragma unroll
        for (int qi = 0; qi < QB; qi++) acc[qi] = make_float2(0.f, 0.f);
        const float* vbase = qkv + 2 * DIM + h * HD + d2 * 2;
        for (int kk = part; kk < keyLen; kk += 8) {
            float2 v = *(const float2*)(vbase + (size_t)(base + kk) * QKVD);
            #pragma unroll
            for (int qi = 0; qi < QB; qi++) {
                float p = sc[qi * keyLenP + kk];   // padded rows are exactly 0
                acc[qi].x += p * v.x;
                acc[qi].y += p * v.y;
            }
        }
        #pragma unroll
        for (int qi = 0; qi < QB; qi++)
            *(float2*)(red + (part * QB + qi) * HD + d2 * 2) = acc[qi];
        __syncthreads();
        if (part == 0) {
            for (int qi = 0; qi < nq; qi++) {
                float sx = 0.f, sy = 0.f;
                #pragma unroll
                for (int pp = 0; pp < 8; pp++) {
                    float2 r = *(const float2*)(red + (pp * QB + qi) * HD + d2 * 2);
                    sx += r.x; sy += r.y;
                }
                float inv = 1.f / wsum[qi];
                sx *= inv; sy *= inv;
                if (vmean) {
                    sx += vmean[hseg * HD + d2 * 2];
                    sy += vmean[hseg * HD + d2 * 2 + 1];
                }
                size_t o = (size_t)(base + q0 + qi) * DIM + h * HD + d2 * 2;
                split1(sx, ohi[o],     olo[o]);
                split1(sy, ohi[o + 1], olo[o + 1]);
            }
        }
    }
}

// ---------------- host ----------------
static void run_mma(const unsigned short* Ahi, const unsigned short* Alo,
                    const unsigned short* Bhi, const unsigned short* Blo,
                    const float* bias, const float* res, float* C,
                    unsigned short* Chi, unsigned short* Clo,
                    int M, int N, int K, int act) {
    dim3 grid(N / 128, (M + 63) / 64);
    mma_gemm<<<grid, 256, NSTG * STG>>>(Ahi, Alo, Bhi, Blo, bias, res, C, Chi, Clo, M, N, K, act);
}

extern "C" void kernel_launch(void* const* d_in, const int* in_sizes, int n_in,
                              void* d_out, int out_size) {
    const float* x       = (const float*)d_in[0];
    const float* W_patch = (const float*)d_in[1];
    const float* b_patch = (const float*)d_in[2];
    const float* cls     = (const float*)d_in[3];
    const float* pos     = (const float*)d_in[4];
    const float* ln1_g   = (const float*)d_in[5];
    const float* ln1_b   = (const float*)d_in[6];
    const float* qkv_w   = (const float*)d_in[7];
    const float* qkv_b   = (const float*)d_in[8];
    const float* proj_w  = (const float*)d_in[9];
    const float* proj_b  = (const float*)d_in[10];
    const float* ln2_g   = (const float*)d_in[11];
    const float* ln2_b   = (const float*)d_in[12];
    const float* fc1_w   = (const float*)d_in[13];
    const float* fc1_b   = (const float*)d_in[14];
    const float* fc2_w   = (const float*)d_in[15];
    const float* fc2_b   = (const float*)d_in[16];
    const float* lnf_g   = (const float*)d_in[17];
    const float* lnf_b   = (const float*)d_in[18];

    float *emb_, *h_, *qkv_, *vm_;
    unsigned short *pH, *pL, *aH, *aL, *oH, *oL, *mH, *mL;
    unsigned short *wpH, *wpL, *qkH, *qkL, *prH, *prL, *f1H, *f1L, *f2H, *f2L;
    cudaGetSymbolAddress((void**)&emb_, g_emb);
    cudaGetSymbolAddress((void**)&h_,   g_h);
    cudaGetSymbolAddress((void**)&qkv_, g_qkv);
    cudaGetSymbolAddress((void**)&vm_,  g_vmean);
    cudaGetSymbolAddress((void**)&pH, g_p_hi);   cudaGetSymbolAddress((void**)&pL, g_p_lo);
    cudaGetSymbolAddress((void**)&aH, g_a_hi);   cudaGetSymbolAddress((void**)&aL, g_a_lo);
    cudaGetSymbolAddress((void**)&oH, g_o_hi);   cudaGetSymbolAddress((void**)&oL, g_o_lo);
    cudaGetSymbolAddress((void**)&mH, g_m_hi);   cudaGetSymbolAddress((void**)&mL, g_m_lo);
    cudaGetSymbolAddress((void**)&wpH, g_wp_hi); cudaGetSymbolAddress((void**)&wpL, g_wp_lo);
    cudaGetSymbolAddress((void**)&qkH, g_qkvT_hi); cudaGetSymbolAddress((void**)&qkL, g_qkvT_lo);
    cudaGetSymbolAddress((void**)&prH, g_projT_hi); cudaGetSymbolAddress((void**)&prL, g_projT_lo);
    cudaGetSymbolAddress((void**)&f1H, g_fc1T_hi); cudaGetSymbolAddress((void**)&f1L, g_fc1T_lo);
    cudaGetSymbolAddress((void**)&f2H, g_fc2T_hi); cudaGetSymbolAddress((void**)&f2L, g_fc2T_lo);

    cudaFuncSetAttribute(mma_gemm, cudaFuncAttributeMaxDynamicSharedMemorySize, NSTG * STG);

    size_t smem_joint = (size_t)(QB * HD + QB * SEQ  + 8 * QB * HD) * sizeof(float);
    size_t smem_sp    = (size_t)(QB * HD + QB * 200  + 8 * QB * HD) * sizeof(float);
    cudaFuncSetAttribute(attn_kernel, cudaFuncAttributeMaxDynamicSharedMemorySize, (int)smem_joint);

    patch_kernel<<<(1568 * 768 + 255) / 256, 256>>>(x, pH, pL);                       // 0
    split_kernel<<<(DIM * DIM + 255) / 256, 256>>>(W_patch, wpH, wpL, DIM * DIM);     // 1
    dim3 tb(32, 8);
    transpose_split_kernel<<<dim3(QKVD / 32, DIM / 32, 12), tb>>>(qkv_w, qkH, qkL, DIM, QKVD); // 2
    run_mma(pH, pL, wpH, wpL, b_patch, nullptr, emb_, nullptr, nullptr, 1568, 768, 768, 0);    // 3 <- profiled
    transpose_split_kernel<<<dim3(DIM / 32,  DIM / 32, 12), tb>>>(proj_w, prH, prL, DIM, DIM);
    transpose_split_kernel<<<dim3(MLPD / 32, DIM / 32, 12), tb>>>(fc1_w,  f1H, f1L, DIM, MLPD);
    transpose_split_kernel<<<dim3(DIM / 32, MLPD / 32, 12), tb>>>(fc2_w,  f2H, f2L, MLPD, DIM);
    assemble_kernel<<<(SEQ * DIM + 255) / 256, 256>>>(emb_, cls, pos, h_);

    for (int i = 0; i < 12; i++) {
        ln_split_kernel<<<SEQ, 256>>>(h_, ln1_g + i * DIM, ln1_b + i * DIM, aH, aL);
        run_mma(aH, aL, qkH + (size_t)i * QKVD * DIM, qkL + (size_t)i * QKVD * DIM,
                qkv_b + i * QKVD, nullptr, qkv_, nullptr, nullptr, SEQ, QKVD, DIM, 0);
        if ((i & 1) == 0) {
            vmean_kernel<<<NHEAD * TFR, HD>>>(qkv_, vm_);
            dim3 g((NTOK + QB - 1) / QB, NHEAD * TFR);
            attn_kernel<<<g, 256, smem_sp>>>(qkv_, vm_, oH, oL, NTOK, 200, TFR);
        } else {
            dim3 g((SEQ + QB - 1) / QB, NHEAD);
            attn_kernel<<<g, 256, smem_joint>>>(qkv_, nullptr, oH, oL, SEQ, SEQ, 1);
        }
        run_mma(oH, oL, prH + (size_t)i * DIM * DIM, prL + (size_t)i * DIM * DIM,
                proj_b + i * DIM, h_, h_, nullptr, nullptr, SEQ, DIM, DIM, 0);
        ln_split_kernel<<<SEQ, 256>>>(h_, ln2_g + i * DIM, ln2_b + i * DIM, aH, aL);
        run_mma(aH, aL, f1H + (size_t)i * MLPD * DIM, f1L + (size_t)i * MLPD * DIM,
                fc1_b + i * MLPD, nullptr, nullptr, mH, mL, SEQ, MLPD, DIM, 1);
        run_mma(mH, mL, f2H + (size_t)i * DIM * MLPD, f2L + (size_t)i * DIM * MLPD,
                fc2_b + i * DIM, h_, h_, nullptr, nullptr, SEQ, DIM, MLPD, 0);
    }

    ln_kernel<<<SEQ, 256>>>(h_, lnf_g, lnf_b, (float*)d_out);
}

// round 12
// speedup vs baseline: 1.4077x; 1.0523x over previous
#include <cuda_runtime.h>
#include <cuda_bf16.h>
#include <math.h>
#include <stdint.h>

constexpr int SEQ  = 1576;   // T*N tokens
constexpr int DIM  = 768;
constexpr int NHEAD = 12;
constexpr int HD   = 64;
constexpr int TFR  = 8;      // frames
constexpr int NTOK = 197;    // tokens per frame
constexpr int NPAT = 196;
constexpr int MLPD = 3072;
constexpr int QKVD = 2304;
constexpr float ASCALE = 0.125f;

// ---------------- scratch (no allocation allowed) ----------------
__device__ float g_emb[1568 * 768];
__device__ float g_h[SEQ * DIM];
__device__ float g_qkv[SEQ * QKVD];
__device__ float g_vmean[NHEAD * TFR * HD];
__device__ unsigned short g_p_hi[1568 * 768],  g_p_lo[1568 * 768];
__device__ unsigned short g_a_hi[SEQ * DIM],   g_a_lo[SEQ * DIM];
__device__ unsigned short g_o_hi[SEQ * DIM],   g_o_lo[SEQ * DIM];
__device__ unsigned short g_m_hi[SEQ * MLPD],  g_m_lo[SEQ * MLPD];
__device__ unsigned short g_wp_hi[DIM * DIM],        g_wp_lo[DIM * DIM];
__device__ unsigned short g_qkvT_hi[12 * QKVD * DIM], g_qkvT_lo[12 * QKVD * DIM];
__device__ unsigned short g_projT_hi[12 * DIM * DIM], g_projT_lo[12 * DIM * DIM];
__device__ unsigned short g_fc1T_hi[12 * MLPD * DIM], g_fc1T_lo[12 * MLPD * DIM];
__device__ unsigned short g_fc2T_hi[12 * DIM * MLPD], g_fc2T_lo[12 * DIM * MLPD];

// ================= helpers =================
__device__ __forceinline__ uint32_t smem_u32(const void* p) {
    uint32_t a;
    asm("{ .reg .u64 t; cvta.to.shared.u64 t, %1; cvt.u32.u64 %0, t; }" : "=r"(a) : "l"(p));
    return a;
}
__device__ __forceinline__ void split1(float v, unsigned short& hi, unsigned short& lo) {
    __nv_bfloat16 h = __float2bfloat16(v);
    __nv_bfloat16 l = __float2bfloat16(v - __bfloat162float(h));
    hi = __bfloat16_as_ushort(h);
    lo = __bfloat16_as_ushort(l);
}

#define LDM4(r, addr) \
    asm volatile("ldmatrix.sync.aligned.m8n8.x4.shared.b16 {%0,%1,%2,%3}, [%4];" \
        : "=r"((r)[0]), "=r"((r)[1]), "=r"((r)[2]), "=r"((r)[3]) : "r"(addr))

#define MMA_BF16(c, a, b0, b1) \
    asm volatile("mma.sync.aligned.m16n8k16.row.col.f32.bf16.bf16.f32 " \
        "{%0,%1,%2,%3}, {%4,%5,%6,%7}, {%8,%9}, {%0,%1,%2,%3};" \
        : "+f"((c)[0]), "+f"((c)[1]), "+f"((c)[2]), "+f"((c)[3]) \
        : "r"((a)[0]), "r"((a)[1]), "r"((a)[2]), "r"((a)[3]), "r"(b0), "r"(b1))

#define CPA16(dst, src, sz) \
    asm volatile("cp.async.cg.shared.global [%0], [%1], 16, %2;" \
        :: "r"(dst), "l"(src), "r"(sz))
#define CPA_COMMIT() asm volatile("cp.async.commit_group;")
#define CPA_WAIT1()  asm volatile("cp.async.wait_group 1;")

// ---------------- transpose + split: fp32 [K,N] -> bf16 hi/lo [N,K] ----------------
__global__ void transpose_split_kernel(const float* __restrict__ in,
        unsigned short* __restrict__ ohi, unsigned short* __restrict__ olo, int K, int N) {
    __shared__ float t[32][33];
    size_t base = (size_t)blockIdx.z * K * N;
    int n0 = blockIdx.x * 32, k0 = blockIdx.y * 32;
    int tx = threadIdx.x, ty = threadIdx.y;
    #pragma unroll
    for (int j = 0; j < 32; j += 8)
        t[ty + j][tx] = in[base + (size_t)(k0 + ty + j) * N + n0 + tx];
    __syncthreads();
    #pragma unroll
    for (int j = 0; j < 32; j += 8) {
        unsigned short hi, lo;
        split1(t[tx][ty + j], hi, lo);
        size_t o = base + (size_t)(n0 + ty + j) * K + k0 + tx;
        ohi[o] = hi; olo[o] = lo;
    }
}

// ---------------- elementwise split ----------------
__global__ void split_kernel(const float* __restrict__ in,
        unsigned short* __restrict__ hi, unsigned short* __restrict__ lo, int n) {
    int i = blockIdx.x * blockDim.x + threadIdx.x;
    if (i >= n) return;
    split1(in[i], hi[i], lo[i]);
}

// ===================================================================================
// bf16x3 MMA GEMM (exact round-8/11 best configuration)
// ===================================================================================
constexpr int RS = 80;
constexpr int NSTG = 3;
constexpr int AL_OFF = 64 * RS;
constexpr int BH_OFF = 2 * 64 * RS;
constexpr int BL_OFF = BH_OFF + 128 * RS;
constexpr int STG    = BH_OFF + 2 * 128 * RS;   // 30720

__device__ __forceinline__ void load_stage(uint32_t sb,
        const unsigned short* __restrict__ Ahi, const unsigned short* __restrict__ Alo,
        const unsigned short* __restrict__ Bhi, const unsigned short* __restrict__ Blo,
        int row0, int col0, int K, int k0, int M, int tid) {
    int r = tid >> 2, ch = tid & 3;
    uint32_t doff = (uint32_t)(r * RS + ch * 16);
    size_t asrc = (size_t)(row0 + r) * K + k0 + ch * 8;
    int av = (row0 + r < M) ? 16 : 0;
    CPA16(sb + doff, Ahi + asrc, av);
    CPA16(sb + AL_OFF + doff, Alo + asrc, av);
    size_t b0 = (size_t)(col0 + r) * K + k0 + ch * 8;
    size_t b1 = (size_t)(col0 + 64 + r) * K + k0 + ch * 8;
    CPA16(sb + BH_OFF + doff, Bhi + b0, 16);
    CPA16(sb + BH_OFF + doff + 64 * RS, Bhi + b1, 16);
    CPA16(sb + BL_OFF + doff, Blo + b0, 16);
    CPA16(sb + BL_OFF + doff + 64 * RS, Blo + b1, 16);
    CPA_COMMIT();
}

__global__ void __launch_bounds__(256, 2) mma_gemm(
        const unsigned short* __restrict__ Ahi, const unsigned short* __restrict__ Alo,
        const unsigned short* __restrict__ Bhi, const unsigned short* __restrict__ Blo,
        const float* __restrict__ bias, const float* __restrict__ res,
        float* __restrict__ C, unsigned short* __restrict__ Chi,
        unsigned short* __restrict__ Clo,
        int M, int N, int K, int act) {
    extern __shared__ __align__(128) char sm[];
    const int tid = threadIdx.x;
    const int lane = tid & 31, wid = tid >> 5;
    const int wm = wid & 1, wn = wid >> 1;
    const int row0 = blockIdx.y * 64, col0 = blockIdx.x * 128;
    const uint32_t smb = smem_u32(sm);

    const int a_row = ((lane >> 3) & 1) * 8 + (lane & 7);
    const int a_kb  = (lane >> 4) * 16;
    const int b_row = (lane >> 4) * 8 + (lane & 7);
    const int b_kb  = ((lane >> 3) & 1) * 16;

    float c[2][4][4];
    #pragma unroll
    for (int i = 0; i < 2; i++)
        #pragma unroll
        for (int j = 0; j < 4; j++)
            #pragma unroll
            for (int k = 0; k < 4; k++) c[i][j][k] = 0.f;

    const int nk = K >> 5;
    load_stage(smb, Ahi, Alo, Bhi, Blo, row0, col0, K, 0, M, tid);
    load_stage(smb + STG, Ahi, Alo, Bhi, Blo, row0, col0, K, 32, M, tid);

    int buf = 0;
    for (int it = 0; it < nk; it++) {
        CPA_WAIT1();
        __syncthreads();
        if (it + 2 < nk) {
            int nb = buf + 2; if (nb >= NSTG) nb -= NSTG;
            load_stage(smb + (uint32_t)nb * STG, Ahi, Alo, Bhi, Blo,
                       row0, col0, K, (it + 2) << 5, M, tid);
        }
        uint32_t sb = smb + (uint32_t)buf * STG;
        #pragma unroll
        for (int kk = 0; kk < 2; kk++) {
            uint32_t bh[8], bl[8];
            #pragma unroll
            for (int nip = 0; nip < 2; nip++) {
                uint32_t baddr = sb + BH_OFF + (wn * 32 + nip * 16 + b_row) * RS + b_kb + kk * 32;
                LDM4(&bh[nip * 4], baddr);
                LDM4(&bl[nip * 4], baddr + (BL_OFF - BH_OFF));
            }
            #pragma unroll
            for (int mi = 0; mi < 2; mi++) {
                uint32_t ah[4], al[4];
                uint32_t aaddr = sb + (wm * 32 + mi * 16 + a_row) * RS + a_kb + kk * 32;
                LDM4(ah, aaddr);
                LDM4(al, aaddr + AL_OFF);
                #pragma unroll
                for (int ni = 0; ni < 4; ni++) {
                    uint32_t b0h = bh[(ni >> 1) * 4 + (ni & 1) * 2];
                    uint32_t b1h = bh[(ni >> 1) * 4 + (ni & 1) * 2 + 1];
                    uint32_t b0l = bl[(ni >> 1) * 4 + (ni & 1) * 2];
                    uint32_t b1l = bl[(ni >> 1) * 4 + (ni & 1) * 2 + 1];
                    MMA_BF16(c[mi][ni], ah, b0h, b1h);
                    MMA_BF16(c[mi][ni], ah, b0l, b1l);
                    MMA_BF16(c[mi][ni], al, b0h, b1h);
                }
            }
        }
        buf++; if (buf >= NSTG) buf = 0;
    }

    // ---- epilogue ----
    const int g = lane >> 2, t = lane & 3;
    #pragma unroll
    for (int mi = 0; mi < 2; mi++) {
        #pragma unroll
        for (int ni = 0; ni < 4; ni++) {
            int col = col0 + wn * 32 + ni * 8 + t * 2;
            float2 bb = bias ? *(const float2*)(bias + col) : make_float2(0.f, 0.f);
            #pragma unroll
            for (int half = 0; half < 2; half++) {
                int gm = row0 + wm * 32 + mi * 16 + g + half * 8;
                if (gm >= M) continue;
                float v0 = c[mi][ni][half * 2 + 0] + bb.x;
                float v1 = c[mi][ni][half * 2 + 1] + bb.y;
                if (act) {
                    v0 = 0.5f * v0 * (1.f + erff(v0 * 0.70710678118f));
                    v1 = 0.5f * v1 * (1.f + erff(v1 * 0.70710678118f));
                }
                if (res) {
                    float2 rv = *(const float2*)(res + (size_t)gm * N + col);
                    v0 += rv.x; v1 += rv.y;
                }
                size_t o = (size_t)gm * N + col;
                if (Chi) {
                    unsigned short h0, l0, h1, l1;
                    split1(v0, h0, l0);
                    split1(v1, h1, l1);
                    *(uint32_t*)(Chi + o) = (uint32_t)h0 | ((uint32_t)h1 << 16);
                    *(uint32_t*)(Clo + o) = (uint32_t)l0 | ((uint32_t)l1 << 16);
                } else {
                    *(float2*)(C + o) = make_float2(v0, v1);
                }
            }
        }
    }
}

// ---------------- patch extraction -> bf16 hi/lo ----------------
__global__ void patch_kernel(const float* __restrict__ x,
        unsigned short* __restrict__ Phi, unsigned short* __restrict__ Plo) {
    int idx = blockIdx.x * blockDim.x + threadIdx.x;
    if (idx >= 1568 * 768) return;
    int m = idx / 768, kcol = idx % 768;
    int t = m / 196, n = m % 196;
    int hp = n / 14, wp = n % 14;
    int c = kcol / 256, rem = kcol % 256;
    int ii = rem / 16, jj = rem % 16;
    float v = x[((t * 3 + c) * 224 + hp * 16 + ii) * 224 + wp * 16 + jj];
    split1(v, Phi[idx], Plo[idx]);
}

// ---------------- assemble h ----------------
__global__ void assemble_kernel(const float* __restrict__ emb, const float* __restrict__ cls,
                                const float* __restrict__ pos, float* __restrict__ h) {
    int idx = blockIdx.x * blockDim.x + threadIdx.x;
    if (idx >= SEQ * DIM) return;
    int m = idx / DIM, dd = idx % DIM;
    int t = m / NTOK, r = m % NTOK;
    float v;
    if (r == 0) {
        v = cls[dd] + pos[dd];
    } else {
        int pp = r - 1;
        int f = pp * DIM + dd;
        int n = f % NPAT, dc = f / NPAT;
        v = emb[(t * NPAT + n) * DIM + dc] + pos[(1 + pp) * DIM + dd];
    }
    h[idx] = v;
}

// ---------------- block reduction ----------------
__device__ __forceinline__ float block_sum256(float v, float* sh) {
    #pragma unroll
    for (int o = 16; o; o >>= 1) v += __shfl_xor_sync(0xffffffffu, v, o);
    if ((threadIdx.x & 31) == 0) sh[threadIdx.x >> 5] = v;
    __syncthreads();
    float t = 0.f;
    #pragma unroll
    for (int i = 0; i < 8; i++) t += sh[i];
    __syncthreads();
    return t;
}

// ---------------- LayerNorm -> bf16 hi/lo ----------------
__global__ void ln_split_kernel(const float* __restrict__ x, const float* __restrict__ g,
        const float* __restrict__ b, unsigned short* __restrict__ yhi,
        unsigned short* __restrict__ ylo) {
    __shared__ float sh[8];
    int row = blockIdx.x, tid = threadIdx.x;
    const float* xr = x + (size_t)row * DIM;
    float v0 = xr[tid], v1 = xr[tid + 256], v2 = xr[tid + 512];
    float mean = block_sum256(v0 + v1 + v2, sh) * (1.f / DIM);
    float d0 = v0 - mean, d1 = v1 - mean, d2 = v2 - mean;
    float var = block_sum256(d0 * d0 + d1 * d1 + d2 * d2, sh) * (1.f / DIM);
    float inv = rsqrtf(var + 1e-5f);
    size_t o = (size_t)row * DIM + tid;
    float y0 = d0 * inv * g[tid]       + b[tid];
    float y1 = d1 * inv * g[tid + 256] + b[tid + 256];
    float y2 = d2 * inv * g[tid + 512] + b[tid + 512];
    split1(y0, yhi[o],       ylo[o]);
    split1(y1, yhi[o + 256], ylo[o + 256]);
    split1(y2, yhi[o + 512], ylo[o + 512]);
}

// ---------------- final LayerNorm (fp32 out) ----------------
__global__ void ln_kernel(const float* __restrict__ x, const float* __restrict__ g,
                          const float* __restrict__ b, float* __restrict__ y) {
    __shared__ float sh[8];
    int row = blockIdx.x, tid = threadIdx.x;
    const float* xr = x + (size_t)row * DIM;
    float v0 = xr[tid], v1 = xr[tid + 256], v2 = xr[tid + 512];
    float mean = block_sum256(v0 + v1 + v2, sh) * (1.f / DIM);
    float d0 = v0 - mean, d1 = v1 - mean, d2 = v2 - mean;
    float var = block_sum256(d0 * d0 + d1 * d1 + d2 * d2, sh) * (1.f / DIM);
    float inv = rsqrtf(var + 1e-5f);
    float* yr = y + (size_t)row * DIM;
    yr[tid]       = d0 * inv * g[tid]       + b[tid];
    yr[tid + 256] = d1 * inv * g[tid + 256] + b[tid + 256];
    yr[tid + 512] = d2 * inv * g[tid + 512] + b[tid + 512];
}

// ---------------- temporal v-mean ----------------
__global__ void vmean_kernel(const float* __restrict__ qkv, float* __restrict__ vmean) {
    int ht = blockIdx.x;
    int t = ht % TFR, h = ht / TFR;
    int d = threadIdx.x;
    float s = 0.f;
    for (int n = 0; n < NTOK; n++)
        s += qkv[(size_t)(t * NTOK + n) * QKVD + 2 * DIM + h * HD + d];
    vmean[ht * HD + d] = s * (1.f / NTOK);
}

// ---------------- attention, templated on query-block / threads / keys-per-thread ----
// QBT queries per block; NPART = NTHR/32 key-partitions for AV; warp w owns query w
// for softmax and final reduce. sc rows for padded queries are exactly 0.
template <int QBT, int NTHR, int KCH>
__global__ void __launch_bounds__(NTHR) attn_kernel(
        const float* __restrict__ qkv, const float* __restrict__ vmean,
        unsigned short* __restrict__ ohi, unsigned short* __restrict__ olo,
        int keyLen, int keyLenP, int numSeg) {
    constexpr int NPART = NTHR / 32;
    extern __shared__ float smf[];
    float* qs  = smf;                        // QBT*HD
    float* sc  = smf + QBT * HD;             // QBT*keyLenP
    float* red = sc + QBT * keyLenP;         // NPART*QBT*HD
    __shared__ float wsum[QBT];
    int tid = threadIdx.x;
    int hseg = blockIdx.y;
    int h = hseg / numSeg, seg = hseg % numSeg;
    int base = seg * keyLen;
    int q0 = blockIdx.x * QBT;
    int nq = min(QBT, keyLen - q0);

    for (int i = tid; i < QBT * HD; i += NTHR) {
        int qi = i / HD, d = i % HD;
        qs[i] = (qi < nq) ? qkv[(size_t)(base + q0 + qi) * QKVD + h * HD + d] : 0.f;
    }
    __syncthreads();

    // ---- scores: KCH keys per thread, K fragments in registers ----
    const int nkb = (keyLen + KCH - 1) / KCH;
    for (int kb = tid; kb < nkb; kb += NTHR) {
        int kk = kb * KCH;
        float acc[QBT][KCH];
        #pragma unroll
        for (int qi = 0; qi < QBT; qi++)
            #pragma unroll
            for (int c = 0; c < KCH; c++) acc[qi][c] = 0.f;
        const float* kbase0 = qkv + (size_t)(base + kk) * QKVD + DIM + h * HD;
        int voff[KCH];
        #pragma unroll
        for (int c = 0; c < KCH; c++) voff[c] = (kk + c < keyLen) ? c : 0;
        #pragma unroll 4
        for (int j = 0; j < 16; j++) {
            float4 kf[KCH];
            #pragma unroll
            for (int c = 0; c < KCH; c++)
                kf[c] = *(const float4*)(kbase0 + (size_t)voff[c] * QKVD + j * 4);
            #pragma unroll
            for (int qi = 0; qi < QBT; qi++) {
                float4 q = *(const float4*)(qs + qi * HD + j * 4);
                #pragma unroll
                for (int c = 0; c < KCH; c++)
                    acc[qi][c] += q.x * kf[c].x + q.y * kf[c].y
                                + q.z * kf[c].z + q.w * kf[c].w;
            }
        }
        #pragma unroll
        for (int qi = 0; qi < QBT; qi++) {
            float* dst = sc + qi * keyLenP + kk;
            if (kk + KCH <= keyLen) {
                #pragma unroll
                for (int c = 0; c < KCH; c++) dst[c] = acc[qi][c] * ASCALE;
            } else {
                for (int c = 0; c < KCH; c++)
                    if (kk + c < keyLen) dst[c] = acc[qi][c] * ASCALE;
            }
        }
    }
    __syncthreads();

    // ---- softmax: warp w handles query w ----
    int w = tid >> 5, lane = tid & 31;
    if (w < nq) {
        float mx = -1e30f;
        for (int kk = lane; kk < keyLen; kk += 32) mx = fmaxf(mx, sc[w * keyLenP + kk]);
        #pragma unroll
        for (int off = 16; off; off >>= 1) mx = fmaxf(mx, __shfl_xor_sync(0xffffffffu, mx, off));
        float sum = 0.f;
        for (int kk = lane; kk < keyLen; kk += 32) {
            float e = __expf(sc[w * keyLenP + kk] - mx);
            sc[w * keyLenP + kk] = e;
            sum += e;
        }
        #pragma unroll
        for (int off = 16; off; off >>= 1) sum += __shfl_xor_sync(0xffffffffu, sum, off);
        if (lane == 0) wsum[w] = sum;
    }
    __syncthreads();

    // ---- AV: NPART key-partitions (one per warp), float2 V loads ----
    {
        int d2 = lane;            // dims 2*d2, 2*d2+1
        int part = w;
        float2 acc[QBT];
        #pragma unroll
        for (int qi = 0; qi < QBT; qi++) acc[qi] = make_float2(0.f, 0.f);
        const float* vbase = qkv + 2 * DIM + h * HD + d2 * 2;
        for (int kk = part; kk < keyLen; kk += NPART) {
            float2 v = *(const float2*)(vbase + (size_t)(base + kk) * QKVD);
            #pragma unroll
            for (int qi = 0; qi < QBT; qi++) {
                float p = sc[qi * keyLenP + kk];
                acc[qi].x += p * v.x;
                acc[qi].y += p * v.y;
            }
        }
        #pragma unroll
        for (int qi = 0; qi < QBT; qi++)
            *(float2*)(red + (part * QBT + qi) * HD + d2 * 2) = acc[qi];
        __syncthreads();
        // final reduce: warp w reduces query w
        if (w < nq) {
            int qi = w;
            float sx = 0.f, sy = 0.f;
            #pragma unroll
            for (int pp = 0; pp < NPART; pp++) {
                float2 r = *(const float2*)(red + (pp * QBT + qi) * HD + d2 * 2);
                sx += r.x; sy += r.y;
            }
            float inv = 1.f / wsum[qi];
            sx *= inv; sy *= inv;
            if (vmean) {
                sx += vmean[hseg * HD + d2 * 2];
                sy += vmean[hseg * HD + d2 * 2 + 1];
            }
            size_t o = (size_t)(base + q0 + qi) * DIM + h * HD + d2 * 2;
            split1(sx, ohi[o],     olo[o]);
            split1(sy, ohi[o + 1], olo[o + 1]);
        }
    }
}

// ---------------- host ----------------
static void run_mma(const unsigned short* Ahi, const unsigned short* Alo,
                    const unsigned short* Bhi, const unsigned short* Blo,
                    const float* bias, const float* res, float* C,
                    unsigned short* Chi, unsigned short* Clo,
                    int M, int N, int K, int act) {
    dim3 grid(N / 128, (M + 63) / 64);
    mma_gemm<<<grid, 256, NSTG * STG>>>(Ahi, Alo, Bhi, Blo, bias, res, C, Chi, Clo, M, N, K, act);
}

extern "C" void kernel_launch(void* const* d_in, const int* in_sizes, int n_in,
                              void* d_out, int out_size) {
    const float* x       = (const float*)d_in[0];
    const float* W_patch = (const float*)d_in[1];
    const float* b_patch = (const float*)d_in[2];
    const float* cls     = (const float*)d_in[3];
    const float* pos     = (const float*)d_in[4];
    const float* ln1_g   = (const float*)d_in[5];
    const float* ln1_b   = (const float*)d_in[6];
    const float* qkv_w   = (const float*)d_in[7];
    const float* qkv_b   = (const float*)d_in[8];
    const float* proj_w  = (const float*)d_in[9];
    const float* proj_b  = (const float*)d_in[10];
    const float* ln2_g   = (const float*)d_in[11];
    const float* ln2_b   = (const float*)d_in[12];
    const float* fc1_w   = (const float*)d_in[13];
    const float* fc1_b   = (const float*)d_in[14];
    const float* fc2_w   = (const float*)d_in[15];
    const float* fc2_b   = (const float*)d_in[16];
    const float* lnf_g   = (const float*)d_in[17];
    const float* lnf_b   = (const float*)d_in[18];

    float *emb_, *h_, *qkv_, *vm_;
    unsigned short *pH, *pL, *aH, *aL, *oH, *oL, *mH, *mL;
    unsigned short *wpH, *wpL, *qkH, *qkL, *prH, *prL, *f1H, *f1L, *f2H, *f2L;
    cudaGetSymbolAddress((void**)&emb_, g_emb);
    cudaGetSymbolAddress((void**)&h_,   g_h);
    cudaGetSymbolAddress((void**)&qkv_, g_qkv);
    cudaGetSymbolAddress((void**)&vm_,  g_vmean);
    cudaGetSymbolAddress((void**)&pH, g_p_hi);   cudaGetSymbolAddress((void**)&pL, g_p_lo);
    cudaGetSymbolAddress((void**)&aH, g_a_hi);   cudaGetSymbolAddress((void**)&aL, g_a_lo);
    cudaGetSymbolAddress((void**)&oH, g_o_hi);   cudaGetSymbolAddress((void**)&oL, g_o_lo);
    cudaGetSymbolAddress((void**)&mH, g_m_hi);   cudaGetSymbolAddress((void**)&mL, g_m_lo);
    cudaGetSymbolAddress((void**)&wpH, g_wp_hi); cudaGetSymbolAddress((void**)&wpL, g_wp_lo);
    cudaGetSymbolAddress((void**)&qkH, g_qkvT_hi); cudaGetSymbolAddress((void**)&qkL, g_qkvT_lo);
    cudaGetSymbolAddress((void**)&prH, g_projT_hi); cudaGetSymbolAddress((void**)&prL, g_projT_lo);
    cudaGetSymbolAddress((void**)&f1H, g_fc1T_hi); cudaGetSymbolAddress((void**)&f1L, g_fc1T_lo);
    cudaGetSymbolAddress((void**)&f2H, g_fc2T_hi); cudaGetSymbolAddress((void**)&f2L, g_fc2T_lo);

    cudaFuncSetAttribute(mma_gemm, cudaFuncAttributeMaxDynamicSharedMemorySize, NSTG * STG);

    // spatial: QBT=8, 256 thr, KCH=4, keyLen=197 (pad 200)
    size_t smem_sp = (size_t)(8 * HD + 8 * 200 + 8 * 8 * HD) * sizeof(float);
    // joint: QBT=16, 512 thr, KCH=2, keyLen=SEQ
    size_t smem_joint = (size_t)(16 * HD + 16 * SEQ + 16 * 16 * HD) * sizeof(float);
    cudaFuncSetAttribute((const void*)attn_kernel<16, 512, 2>,
                         cudaFuncAttributeMaxDynamicSharedMemorySize, (int)smem_joint);
    cudaFuncSetAttribute((const void*)attn_kernel<8, 256, 4>,
                         cudaFuncAttributeMaxDynamicSharedMemorySize, (int)smem_sp);

    patch_kernel<<<(1568 * 768 + 255) / 256, 256>>>(x, pH, pL);                       // 0
    split_kernel<<<(DIM * DIM + 255) / 256, 256>>>(W_patch, wpH, wpL, DIM * DIM);     // 1
    dim3 tb(32, 8);
    transpose_split_kernel<<<dim3(QKVD / 32, DIM / 32, 12), tb>>>(qkv_w, qkH, qkL, DIM, QKVD); // 2
    run_mma(pH, pL, wpH, wpL, b_patch, nullptr, emb_, nullptr, nullptr, 1568, 768, 768, 0);    // 3 <- profiled
    transpose_split_kernel<<<dim3(DIM / 32,  DIM / 32, 12), tb>>>(proj_w, prH, prL, DIM, DIM);
    transpose_split_kernel<<<dim3(MLPD / 32, DIM / 32, 12), tb>>>(fc1_w,  f1H, f1L, DIM, MLPD);
    transpose_split_kernel<<<dim3(DIM / 32, MLPD / 32, 12), tb>>>(fc2_w,  f2H, f2L, MLPD, DIM);
    assemble_kernel<<<(SEQ * DIM + 255) / 256, 256>>>(emb_, cls, pos, h_);

    for (int i = 0; i < 12; i++) {
        ln_split_kernel<<<SEQ, 256>>>(h_, ln1_g + i * DIM, ln1_b + i * DIM, aH, aL);
        run_mma(aH, aL, qkH + (size_t)i * QKVD * DIM, qkL + (size_t)i * QKVD * DIM,
                qkv_b + i * QKVD, nullptr, qkv_, nullptr, nullptr, SEQ, QKVD, DIM, 0);
        if ((i & 1) == 0) {
            vmean_kernel<<<NHEAD * TFR, HD>>>(qkv_, vm_);
            dim3 g((NTOK + 7) / 8, NHEAD * TFR);
            attn_kernel<8, 256, 4><<<g, 256, smem_sp>>>(qkv_, vm_, oH, oL, NTOK, 200, TFR);
        } else {
            dim3 g((SEQ + 15) / 16, NHEAD);
            attn_kernel<16, 512, 2><<<g, 512, smem_joint>>>(qkv_, nullptr, oH, oL, SEQ, SEQ, 1);
        }
        run_mma(oH, oL, prH + (size_t)i * DIM * DIM, prL + (size_t)i * DIM * DIM,
                proj_b + i * DIM, h_, h_, nullptr, nullptr, SEQ, DIM, DIM, 0);
        ln_split_kernel<<<SEQ, 256>>>(h_, ln2_g + i * DIM, ln2_b + i * DIM, aH, aL);
        run_mma(aH, aL, f1H + (size_t)i * MLPD * DIM, f1L + (size_t)i * MLPD * DIM,
                fc1_b + i * MLPD, nullptr, nullptr, mH, mL, SEQ, MLPD, DIM, 1);
        run_mma(mH, mL, f2H + (size_t)i * DIM * MLPD, f2L + (size_t)i * DIM * MLPD,
                fc2_b + i * DIM, h_, h_, nullptr, nullptr, SEQ, DIM, MLPD, 0);
    }

    ln_kernel<<<SEQ, 256>>>(h_, lnf_g, lnf_b, (float*)d_out);
}